// round 12
// baseline (speedup 1.0000x reference)
#include <cuda_runtime.h>
#include <math.h>
#include <stdint.h>

#define FULLMASK 0xffffffffu

static const int B  = 8;
static const int N0 = 4096;
static const int N1 = 1024;
static const int N2 = 256;

// ---------------- scratch (device globals) ----------------------------------
__device__ float d_feat0[B*N0*8];      // (B,N0,8)  channels-last
__device__ float d_kf1  [B*N0*32];     // (B,N0,32) channels-last
__device__ float d_qc1  [B*3*N1];      // (B,3,N1)  channels-first
__device__ float d_qf2  [B*N1*64];     // (B,N1,64)
__device__ float d_kf3  [B*N1*64];     // (B,N1,64)
__device__ float d_hmax [B*N0*32];     // per-(b,q,o) max_k h (reused per layer)
__device__ float d_hmin [B*N0*32];
__device__ int   d_nidx [B*N0*16];     // knn layer1/2 indices
__device__ int   d_nidx2[B*N1*16];     // knn layer3
__device__ int   d_nidx3[B*N2*16];     // knn layer4
__device__ int   d_fidx [B*N1];        // fps1 indices
__device__ int   d_fidx2[B*N2];        // fps2 indices (local into N1 subset)
__device__ float d_gsum [4*B*4];
__device__ float d_gsq  [4*B*4];

// ---------------- warp redux / barrier helpers --------------------------------
__device__ __forceinline__ unsigned redux_max_u32(unsigned v) {
    unsigned r; asm("redux.sync.max.u32 %0, %1, 0xffffffff;" : "=r"(r) : "r"(v)); return r;
}
__device__ __forceinline__ unsigned redux_min_u32(unsigned v) {
    unsigned r; asm("redux.sync.min.u32 %0, %1, 0xffffffff;" : "=r"(r) : "r"(v)); return r;
}
__device__ __forceinline__ void bar_named(int id) {
    asm volatile("bar.sync %0, 256;" :: "r"(id) : "memory");
}

// ---------------- packed f32x2 helpers ----------------------------------------
__device__ __forceinline__ unsigned long long pack2(float lo, float hi) {
    unsigned long long v;
    asm("mov.b64 %0, {%1, %2};" : "=l"(v) : "f"(lo), "f"(hi));
    return v;
}
// d = ((x-lx)^2 + (y-ly)^2) + (z-lz)^2 for two points, per-lane rn arithmetic
// (add of negated value == sub, mul/add rounding identical to scalar path).
__device__ __forceinline__ void dist2_pair(
    unsigned long long px2, unsigned long long py2, unsigned long long pz2,
    unsigned long long nlx2, unsigned long long nly2, unsigned long long nlz2,
    float& d0, float& d1)
{
    unsigned long long dx, dy, dz, s;
    asm("add.rn.f32x2 %0, %1, %2;" : "=l"(dx) : "l"(px2), "l"(nlx2));
    asm("add.rn.f32x2 %0, %1, %2;" : "=l"(dy) : "l"(py2), "l"(nly2));
    asm("add.rn.f32x2 %0, %1, %2;" : "=l"(dz) : "l"(pz2), "l"(nlz2));
    asm("mul.rn.f32x2 %0, %1, %1;" : "=l"(dx) : "l"(dx));
    asm("mul.rn.f32x2 %0, %1, %1;" : "=l"(dy) : "l"(dy));
    asm("mul.rn.f32x2 %0, %1, %1;" : "=l"(dz) : "l"(dz));
    asm("add.rn.f32x2 %0, %1, %2;" : "=l"(s)  : "l"(dx), "l"(dy));
    asm("add.rn.f32x2 %0, %1, %2;" : "=l"(s)  : "l"(s),  "l"(dz));
    asm("mov.b64 {%0, %1}, %2;" : "=f"(d0), "=f"(d1) : "l"(s));
}

// thread-local argmax over dd[NPT]: max via FMNMX tree, then min encoded index
// among exact-equal values (matches scan-order tie-break).
template<int NPT>
__device__ __forceinline__ void fps_argmax(const float* dd, int t, float& bv, int& bi)
{
    float m[NPT];
    #pragma unroll
    for (int p = 0; p < NPT; p++) m[p] = dd[p];
    #pragma unroll
    for (int s = NPT/2; s > 0; s >>= 1)
        #pragma unroll
        for (int p = 0; p < s; p++) m[p] = fmaxf(m[p], m[p+s]);
    bv = m[0];
    int enc[NPT];
    #pragma unroll
    for (int p = 0; p < NPT; p++)
        enc[p] = (dd[p] == bv) ? (t + (p << 8)) : 0x7FFFFFFF;
    #pragma unroll
    for (int s = NPT/2; s > 0; s >>= 1)
        #pragma unroll
        for (int p = 0; p < s; p++) enc[p] = min(enc[p], enc[p+s]);
    bi = enc[0];
}

// post-barrier 8-slot winner: pairwise u64 tree (depth 3)
__device__ __forceinline__ int fps_block_winner(const unsigned long long* slot)
{
    unsigned long long v0 = slot[0], v1 = slot[1], v2 = slot[2], v3 = slot[3];
    unsigned long long v4 = slot[4], v5 = slot[5], v6 = slot[6], v7 = slot[7];
    unsigned long long a = (v0 > v1) ? v0 : v1;
    unsigned long long b = (v2 > v3) ? v2 : v3;
    unsigned long long c = (v4 > v5) ? v4 : v5;
    unsigned long long d = (v6 > v7) ? v6 : v7;
    a = (a > b) ? a : b;
    c = (c > d) ? c : d;
    a = (a > c) ? a : c;
    return (int)(~(unsigned)a);
}

// ---------------- dual-FPS: one 256-thread group does fps1 then fps2 ----------
// Group g of the block handles batch b. Named barrier (1+g) syncs the group.
// Selected coords stashed in s_sel (3*N1 floats) during fps1; fps2 runs on them.
__device__ void fps_dual(const float* __restrict__ pc, int b, int g,
                         float* s_sel, unsigned long long* s_win,
                         int* __restrict__ outidx1, int* __restrict__ outidx2)
{
    const int t = threadIdx.x & 255;
    const int barid = 1 + g;
    float* s_sx = s_sel;
    float* s_sy = s_sel + N1;
    float* s_sz = s_sel + 2*N1;
    const float* cx = pc + (b*3+0)*N0;
    const float* cy = pc + (b*3+1)*N0;
    const float* cz = pc + (b*3+2)*N0;

    // ---- fps1: 4096 -> 1024, 16 pts/thread ----
    {
        unsigned long long px2[8], py2[8], pz2[8];
        float dd[16];
        #pragma unroll
        for (int p = 0; p < 8; p++) {
            int i0 = t + ((2*p)   << 8);
            int i1 = t + ((2*p+1) << 8);
            px2[p] = pack2(cx[i0], cx[i1]);
            py2[p] = pack2(cy[i0], cy[i1]);
            pz2[p] = pack2(cz[i0], cz[i1]);
            dd[2*p] = 1e10f; dd[2*p+1] = 1e10f;
        }
        float lx = cx[0], ly = cy[0], lz = cz[0];
        if (t == 0) {
            outidx1[b*N1] = 0;
            s_sx[0] = lx; s_sy[0] = ly; s_sz[0] = lz;
        }
        for (int it = 1; it < N1; ++it) {
            unsigned long long nlx2 = pack2(-lx, -lx);
            unsigned long long nly2 = pack2(-ly, -ly);
            unsigned long long nlz2 = pack2(-lz, -lz);
            #pragma unroll
            for (int p = 0; p < 8; p++) {
                float d0, d1;
                dist2_pair(px2[p], py2[p], pz2[p], nlx2, nly2, nlz2, d0, d1);
                dd[2*p]   = fminf(dd[2*p],   d0);
                dd[2*p+1] = fminf(dd[2*p+1], d1);
            }
            float bv; int bi;
            fps_argmax<16>(dd, t, bv, bi);
            unsigned db = __float_as_uint(bv);
            unsigned m  = redux_max_u32(db);
            unsigned mi = redux_min_u32(db == m ? (unsigned)bi : 0xFFFFFFFFu);
            int cur = it & 1;
            if ((t & 31) == 0)
                s_win[cur*8 + (t >> 5)] = ((unsigned long long)m << 32) | (unsigned)(~mi);
            bar_named(barid);
            int sel = fps_block_winner(&s_win[cur*8]);
            if (t == 0) outidx1[b*N1 + it] = sel;
            lx = cx[sel]; ly = cy[sel]; lz = cz[sel];
            if (t == 0) { s_sx[it] = lx; s_sy[it] = ly; s_sz[it] = lz; }
        }
    }
    bar_named(barid);   // make s_sel visible to the group

    // ---- fps2: 1024 -> 256 on stashed coords, 4 pts/thread ----
    {
        unsigned long long px2[2], py2[2], pz2[2];
        float dd[4];
        #pragma unroll
        for (int p = 0; p < 2; p++) {
            int i0 = t + ((2*p)   << 8);
            int i1 = t + ((2*p+1) << 8);
            px2[p] = pack2(s_sx[i0], s_sx[i1]);
            py2[p] = pack2(s_sy[i0], s_sy[i1]);
            pz2[p] = pack2(s_sz[i0], s_sz[i1]);
            dd[2*p] = 1e10f; dd[2*p+1] = 1e10f;
        }
        float lx = s_sx[0], ly = s_sy[0], lz = s_sz[0];
        if (t == 0) outidx2[b*N2] = 0;
        for (int it = 1; it < N2; ++it) {
            unsigned long long nlx2 = pack2(-lx, -lx);
            unsigned long long nly2 = pack2(-ly, -ly);
            unsigned long long nlz2 = pack2(-lz, -lz);
            #pragma unroll
            for (int p = 0; p < 2; p++) {
                float d0, d1;
                dist2_pair(px2[p], py2[p], pz2[p], nlx2, nly2, nlz2, d0, d1);
                dd[2*p]   = fminf(dd[2*p],   d0);
                dd[2*p+1] = fminf(dd[2*p+1], d1);
            }
            float bv; int bi;
            fps_argmax<4>(dd, t, bv, bi);
            unsigned db = __float_as_uint(bv);
            unsigned m  = redux_max_u32(db);
            unsigned mi = redux_min_u32(db == m ? (unsigned)bi : 0xFFFFFFFFu);
            int cur = it & 1;
            if ((t & 31) == 0)
                s_win[cur*8 + (t >> 5)] = ((unsigned long long)m << 32) | (unsigned)(~mi);
            bar_named(barid);
            int sel = fps_block_winner(&s_win[cur*8]);
            if (t == 0) outidx2[b*N2 + it] = sel;
            lx = s_sx[sel]; ly = s_sy[sel]; lz = s_sz[sel];
        }
    }
}

// ---------------- KNN: BT queries/block, optional indirection + feat ---------
template<int BT>
__device__ void knn_block(const float* __restrict__ qcoord, int qstride, const int* __restrict__ qidxmap,
                          const float* __restrict__ kcoord, int kstride, const int* __restrict__ kidxmap,
                          int Q, int Kn, int b, int qtile, int* __restrict__ nidx,
                          const int* __restrict__ omap,
                          bool dofeat, const float* __restrict__ Wt, const float* __restrict__ bt,
                          float* __restrict__ feat0)
{
    __shared__ float4 sk[BT];
    const int tid = threadIdx.x;
    int q = qtile*BT + tid;
    int qr = qidxmap ? qidxmap[b*Q + q] : q;
    float x = qcoord[(b*3+0)*qstride + qr];
    float y = qcoord[(b*3+1)*qstride + qr];
    float z = qcoord[(b*3+2)*qstride + qr];
    if (dofeat) {
        float f[8];
        #pragma unroll
        for (int o = 0; o < 8; o++)
            f[o] = fmaf(Wt[o*3+2], z, fmaf(Wt[o*3+1], y, fmaf(Wt[o*3+0], x, bt[o])));
        float4* dst = (float4*)&feat0[((size_t)(b*N0 + q))*8];
        dst[0] = make_float4(f[0], f[1], f[2], f[3]);
        dst[1] = make_float4(f[4], f[5], f[6], f[7]);
    }
    float q2 = __fadd_rn(__fadd_rn(__fmul_rn(x,x), __fmul_rn(y,y)), __fmul_rn(z,z));
    float bd[16]; int bi[16];
    #pragma unroll
    for (int r = 0; r < 16; r++) { bd[r] = 3.4e38f; bi[r] = 0; }
    for (int t0 = 0; t0 < Kn; t0 += BT) {
        int j  = t0 + tid;
        int kr = kidxmap ? kidxmap[b*Kn + j] : j;
        float kx = kcoord[(b*3+0)*kstride + kr];
        float ky = kcoord[(b*3+1)*kstride + kr];
        float kz = kcoord[(b*3+2)*kstride + kr];
        float k2 = __fadd_rn(__fadd_rn(__fmul_rn(kx,kx), __fmul_rn(ky,ky)), __fmul_rn(kz,kz));
        __syncthreads();
        sk[tid] = make_float4(kx, ky, kz, k2);
        __syncthreads();
        #pragma unroll 4
        for (int kk = 0; kk < BT; kk++) {
            float4 s  = sk[kk];
            float dot = __fadd_rn(__fadd_rn(__fmul_rn(x,s.x), __fmul_rn(y,s.y)), __fmul_rn(z,s.z));
            float d2  = __fsub_rn(__fadd_rn(q2, s.w), __fmul_rn(2.0f, dot));
            if (d2 < bd[15]) {
                bd[15] = d2; bi[15] = t0 + kk;
                #pragma unroll
                for (int r = 15; r > 0; --r) {
                    if (bd[r] < bd[r-1]) {
                        float td = bd[r]; bd[r] = bd[r-1]; bd[r-1] = td;
                        int   ti = bi[r]; bi[r] = bi[r-1]; bi[r-1] = ti;
                    }
                }
            }
        }
    }
    #pragma unroll
    for (int r = 0; r < 16; r++) {
        int v = bi[r];
        nidx[((size_t)(b*Q + q))*16 + r] = omap ? omap[b*Kn + v] : v;
    }
}

// ---------------- KNN split: 128 queries/block, 2 threads/query (key halves) --
__device__ void knn_split_block(const float* __restrict__ qc, const float* __restrict__ kc,
                                int b, int qtile, int* __restrict__ nidx)
{
    __shared__ float4 skk[512];
    __shared__ unsigned long long s_k[128][32];
    const int tid  = threadIdx.x;
    const int ql   = tid & 127;
    const int half = tid >> 7;
    int q = qtile*128 + ql;
    float x = qc[(b*3+0)*N1 + q];
    float y = qc[(b*3+1)*N1 + q];
    float z = qc[(b*3+2)*N1 + q];
    float q2 = __fadd_rn(__fadd_rn(__fmul_rn(x,x), __fmul_rn(y,y)), __fmul_rn(z,z));
    float bd[16]; int bi[16];
    #pragma unroll
    for (int r = 0; r < 16; r++) { bd[r] = 3.4e38f; bi[r] = 0; }
    const int kbase = half*2048;
    for (int t0 = 0; t0 < 2048; t0 += 256) {
        {
            int j0 = t0 + tid;
            float kx = kc[(b*3+0)*N0 + j0];
            float ky = kc[(b*3+1)*N0 + j0];
            float kz = kc[(b*3+2)*N0 + j0];
            float k2 = __fadd_rn(__fadd_rn(__fmul_rn(kx,kx), __fmul_rn(ky,ky)), __fmul_rn(kz,kz));
            int j1 = 2048 + t0 + tid;
            float kx1 = kc[(b*3+0)*N0 + j1];
            float ky1 = kc[(b*3+1)*N0 + j1];
            float kz1 = kc[(b*3+2)*N0 + j1];
            float k21 = __fadd_rn(__fadd_rn(__fmul_rn(kx1,kx1), __fmul_rn(ky1,ky1)), __fmul_rn(kz1,kz1));
            __syncthreads();
            skk[tid]       = make_float4(kx,  ky,  kz,  k2);
            skk[256 + tid] = make_float4(kx1, ky1, kz1, k21);
            __syncthreads();
        }
        const float4* sh = skk + half*256;
        #pragma unroll 4
        for (int kk = 0; kk < 256; kk++) {
            float4 s  = sh[kk];
            float dot = __fadd_rn(__fadd_rn(__fmul_rn(x,s.x), __fmul_rn(y,s.y)), __fmul_rn(z,s.z));
            float d2  = __fsub_rn(__fadd_rn(q2, s.w), __fmul_rn(2.0f, dot));
            if (d2 < bd[15]) {
                bd[15] = d2; bi[15] = kbase + t0 + kk;
                #pragma unroll
                for (int r = 15; r > 0; --r) {
                    if (bd[r] < bd[r-1]) {
                        float td = bd[r]; bd[r] = bd[r-1]; bd[r-1] = td;
                        int   ti = bi[r]; bi[r] = bi[r-1]; bi[r-1] = ti;
                    }
                }
            }
        }
    }
    #pragma unroll
    for (int r = 0; r < 16; r++) {
        unsigned dbits = __float_as_uint(bd[r]);
        dbits = (dbits & 0x80000000u) ? ~dbits : (dbits ^ 0x80000000u);   // total order
        s_k[ql][half*16 + r] = ((unsigned long long)dbits << 32) | (unsigned)bi[r];
    }
    __syncthreads();
    if (half == 0) {
        int ia = 0, ib = 0;
        #pragma unroll
        for (int r = 0; r < 16; r++) {
            unsigned long long ka = s_k[ql][min(ia,15)];
            unsigned long long kb = s_k[ql][16 + min(ib,15)];
            bool ta = (ib >= 16) || ((ia < 16) && (ka <= kb));  // tie -> half0 (lower idx)
            unsigned idx = (unsigned)(ta ? ka : kb);
            nidx[((size_t)(b*N1 + q))*16 + r] = (int)idx;
            ia += ta ? 1 : 0; ib += ta ? 0 : 1;
        }
    }
}

// ---------------- edge conv: shared-staged W, h in regs, hmax/hmin + stats ---
template<int CIN, int COUT, int QB>
__device__ void edge_block(float* sws, int eb,
                           const float* __restrict__ qf, int qrows, const int* __restrict__ qmap,
                           const float* __restrict__ kf, int Kn, const int* __restrict__ nidx,
                           const float* __restrict__ W,
                           float* __restrict__ hmax_o, float* __restrict__ hmin_o,
                           float* __restrict__ gsum, float* __restrict__ gsq, int Q)
{
    const int STR = 2*CIN + 4;
    const int NF4 = 2*CIN/4;
    float* s_W  = sws;
    float* s_nb = s_W + COUT*STR;
    float* s_qe = s_nb + QB*16*CIN;
    __shared__ float s_gs[4], s_gq[4];
    const int tid = threadIdx.x;
    const int b  = eb / (Q/QB);
    const int q0 = (eb % (Q/QB)) * QB;
    if (tid < 4) { s_gs[tid] = 0.f; s_gq[tid] = 0.f; }
    for (int i = tid; i < COUT*NF4; i += 256) {
        int o = i / NF4, j = i % NF4;
        *(float4*)&s_W[o*STR + j*4] = ((const float4*)W)[i];
    }
    for (int i = tid; i < QB*(CIN/4); i += 256) {
        int ql = i / (CIN/4), c4 = i % (CIN/4);
        int row = qmap ? qmap[b*Q + q0 + ql] : (q0 + ql);
        float4 v = *(const float4*)&qf[((size_t)b*qrows + row)*CIN + c4*4];
        *(float4*)&s_qe[ql*CIN + c4*4] = v;
    }
    for (int i = tid; i < QB*16*(CIN/4); i += 256) {
        int c4 = i % (CIN/4); int r = i / (CIN/4); int k = r & 15; int ql = r >> 4;
        int nb = nidx[((size_t)(b*Q + q0 + ql))*16 + k];
        float4 v = *(const float4*)&kf[((size_t)(b*Kn) + nb)*CIN + c4*4];
        *(float4*)&s_nb[(ql*16 + k)*CIN + c4*4] = v;
    }
    __syncthreads();
    const int ql = tid / COUT;
    const int o  = tid % COUT;
    float acc[16];
    #pragma unroll
    for (int k = 0; k < 16; k++) acc[k] = 0.f;
    float base = 0.f;
    const float* Wr  = s_W + o*STR;
    const float* qe_ = s_qe + ql*CIN;
    const float* nb_ = s_nb + ql*16*CIN;
    #pragma unroll
    for (int cc = 0; cc < CIN; cc += 4) {
        float4 w  = *(const float4*)&Wr[cc];
        float4 w2 = *(const float4*)&Wr[CIN + cc];
        float4 qe = *(const float4*)&qe_[cc];
        base = fmaf(w2.x - w.x, qe.x, base);
        base = fmaf(w2.y - w.y, qe.y, base);
        base = fmaf(w2.z - w.z, qe.z, base);
        base = fmaf(w2.w - w.w, qe.w, base);
        #pragma unroll
        for (int k = 0; k < 16; k++) {
            float4 nb4 = *(const float4*)&nb_[k*CIN + cc];
            acc[k] = fmaf(w.x, nb4.x, acc[k]);
            acc[k] = fmaf(w.y, nb4.y, acc[k]);
            acc[k] = fmaf(w.z, nb4.z, acc[k]);
            acc[k] = fmaf(w.w, nb4.w, acc[k]);
        }
    }
    float hmx = -3.4e38f, hmn = 3.4e38f, s = 0.f, sq = 0.f;
    #pragma unroll
    for (int k = 0; k < 16; k++) {
        float h = base + acc[k];
        hmx = fmaxf(hmx, h); hmn = fminf(hmn, h);
        s += h; sq = fmaf(h, h, sq);
    }
    const int width = (COUT/4 < 32) ? (COUT/4) : 32;
    #pragma unroll
    for (int off = width >> 1; off; off >>= 1) {
        s  += __shfl_down_sync(FULLMASK, s,  off, width);
        sq += __shfl_down_sync(FULLMASK, sq, off, width);
    }
    int g = o / (COUT/4);
    if ((o & (width-1)) == 0) { atomicAdd(&s_gs[g], s); atomicAdd(&s_gq[g], sq); }
    size_t ofs = ((size_t)(b*Q + q0 + ql))*COUT + o;
    hmax_o[ofs] = hmx; hmin_o[ofs] = hmn;
    __syncthreads();
    if (tid < 4) { atomicAdd(&gsum[b*4+tid], s_gs[tid]); atomicAdd(&gsq[b*4+tid], s_gq[tid]); }
}

// ---------------- finalize: y = leaky(hext*sc + sh) ---------------------------
__device__ void finalize_elem(int lin, const float* __restrict__ hmax, const float* __restrict__ hmin,
                              const float* __restrict__ gsum, const float* __restrict__ gsq,
                              const float* __restrict__ gamma, const float* __restrict__ beta,
                              float* __restrict__ out, int Q, int COUT, float inv_n, bool cf)
{
    int o = lin % COUT; int t = lin / COUT; int q = t % Q; int b = t / Q;
    int g = o / (COUT/4);
    float mean = gsum[b*4+g] * inv_n;
    float var  = gsq [b*4+g] * inv_n - mean*mean;
    float inv  = 1.0f / sqrtf(var + 1e-5f);
    float sc = gamma[o] * inv;
    float sh = beta[o] - mean * sc;
    float hv = (sc >= 0.f) ? hmax[lin] : hmin[lin];
    float yv = hv*sc + sh;
    yv = (yv >= 0.f) ? yv : 0.2f*yv;
    if (cf) out[(b*COUT + o)*Q + q] = yv;
    else    out[lin] = yv;
}

// ---------------- megakernels --------------------------------------------------
// blocks 0-3: dual fps (2 batches each, named-barrier groups); 4-67: knn1 (512t);
// 68: zero stats
__global__ void __launch_bounds__(512) kernelA(const float* __restrict__ pc,
                                               const float* __restrict__ Wt,
                                               const float* __restrict__ bt)
{
    __shared__ float s_sel[2][3*N1];
    __shared__ unsigned long long s_win[2][16];
    int blk = blockIdx.x;
    if (blk < 4) {
        int g = threadIdx.x >> 8;           // group 0/1
        int b = blk + 4*g;                  // batches 0-3 / 4-7
        fps_dual(pc, b, g, s_sel[g], s_win[g], d_fidx, d_fidx2);
    } else if (blk < 68) {
        int r = blk - 4;
        knn_block<512>(pc, N0, nullptr, pc, N0, nullptr, N0, N0, r/8, r%8,
                       d_nidx, nullptr, true, Wt, bt, d_feat0);
    } else {
        int t = threadIdx.x;
        if (t < 128) { d_gsum[t] = 0.f; d_gsq[t] = 0.f; }
    }
}

// edge1 || gather qc1
__global__ void __launch_bounds__(256) kernelB(const float* __restrict__ pc,
                                               const float* __restrict__ W1)
{
    __shared__ float ews[32*20 + 8*16*8 + 8*8];   // edge1 workspace (1728 floats)
    int blk = blockIdx.x;
    if (blk < 4096) {
        edge_block<8,32,8>(ews, blk, d_feat0, N0, nullptr, d_feat0, N0, d_nidx, W1,
                           d_hmax, d_hmin, d_gsum + 0, d_gsq + 0, N0);
    } else {
        int lin = (blk - 4096)*256 + threadIdx.x;      // B*3*N1 = 24576
        int j = lin % N1; int c = (lin/N1) % 3; int b = lin/(3*N1);
        d_qc1[lin] = pc[(b*3+c)*N0 + d_fidx[b*N1 + j]];
    }
}

// knn2(split) || knn3 || knn4 || finalize1
__global__ void __launch_bounds__(256) kernelC(const float* __restrict__ pc,
                                               const float* __restrict__ g1,
                                               const float* __restrict__ b1)
{
    int blk = blockIdx.x;
    if (blk < 64) {
        knn_split_block(d_qc1, pc, blk/8, blk%8, d_nidx);
    } else if (blk < 96) {
        int r = blk - 64;
        knn_block<256>(d_qc1, N1, nullptr, d_qc1, N1, nullptr, N1, N1, r/4, r%4,
                       d_nidx2, nullptr, false, nullptr, nullptr, nullptr);
    } else if (blk < 104) {
        knn_block<256>(d_qc1, N1, d_fidx2, d_qc1, N1, d_fidx2, N2, N2, blk - 96, 0,
                       d_nidx3, d_fidx2, false, nullptr, nullptr, nullptr);
    } else {
        int lin = (blk - 104)*256 + threadIdx.x;       // B*N0*32
        finalize_elem(lin, d_hmax, d_hmin, d_gsum + 0, d_gsq + 0, g1, b1,
                      d_kf1, N0, 32, 1.0f/(8.0f*N0*16.0f), false);
    }
}

__global__ void __launch_bounds__(256) kernelD(const float* __restrict__ W2)
{
    extern __shared__ float dsm[];
    edge_block<32,64,4>(dsm, blockIdx.x, d_kf1, N0, d_fidx, d_kf1, N0, d_nidx, W2,
                        d_hmax, d_hmin, d_gsum + 32, d_gsq + 32, N1);
}

__global__ void __launch_bounds__(256) kernelE(const float* __restrict__ g2,
                                               const float* __restrict__ b2)
{
    int lin = blockIdx.x*256 + threadIdx.x;            // B*N1*64
    finalize_elem(lin, d_hmax, d_hmin, d_gsum + 32, d_gsq + 32, g2, b2,
                  d_qf2, N1, 64, 1.0f/(16.0f*N1*16.0f), false);
}

__global__ void __launch_bounds__(256) kernelF(const float* __restrict__ W3)
{
    extern __shared__ float dsm[];
    edge_block<64,64,4>(dsm, blockIdx.x, d_qf2, N1, nullptr, d_qf2, N1, d_nidx2, W3,
                        d_hmax, d_hmin, d_gsum + 64, d_gsq + 64, N1);
}

__global__ void __launch_bounds__(256) kernelG(const float* __restrict__ g3,
                                               const float* __restrict__ b3,
                                               float* __restrict__ qc_out)
{
    int blk = blockIdx.x;
    if (blk < 2048) {
        int lin = blk*256 + threadIdx.x;               // B*N1*64
        finalize_elem(lin, d_hmax, d_hmin, d_gsum + 64, d_gsq + 64, g3, b3,
                      d_kf3, N1, 64, 1.0f/(16.0f*N1*16.0f), false);
    } else {
        int lin = (blk - 2048)*256 + threadIdx.x;      // B*3*N2 = 6144
        int j = lin % N2; int c = (lin/N2) % 3; int b = lin/(3*N2);
        qc_out[lin] = d_qc1[(b*3+c)*N1 + d_fidx2[b*N2 + j]];
    }
}

__global__ void __launch_bounds__(256) kernelH(const float* __restrict__ W4)
{
    extern __shared__ float dsm[];
    edge_block<64,128,2>(dsm, blockIdx.x, d_kf3, N1, d_fidx2, d_kf3, N1, d_nidx3, W4,
                         d_hmax, d_hmin, d_gsum + 96, d_gsq + 96, N2);
}

__global__ void __launch_bounds__(256) kernelI(const float* __restrict__ g4,
                                               const float* __restrict__ b4,
                                               float* __restrict__ qf_out)
{
    int lin = blockIdx.x*256 + threadIdx.x;            // B*N2*128
    finalize_elem(lin, d_hmax, d_hmin, d_gsum + 96, d_gsq + 96, g4, b4,
                  qf_out, N2, 128, 1.0f/(32.0f*N2*16.0f), true);
}

// ---------------- launch --------------------------------------------------------
extern "C" void kernel_launch(void* const* d_in, const int* in_sizes, int n_in,
                              void* d_out, int out_size) {
    const float* pc = (const float*)d_in[0];
    const float* Wt = (const float*)d_in[1];
    const float* bt = (const float*)d_in[2];
    const float* W1 = (const float*)d_in[3];
    const float* g1 = (const float*)d_in[4];
    const float* b1 = (const float*)d_in[5];
    const float* W2 = (const float*)d_in[6];
    const float* g2 = (const float*)d_in[7];
    const float* b2 = (const float*)d_in[8];
    const float* W3 = (const float*)d_in[9];
    const float* g3 = (const float*)d_in[10];
    const float* b3 = (const float*)d_in[11];
    const float* W4 = (const float*)d_in[12];
    const float* g4 = (const float*)d_in[13];
    const float* b4 = (const float*)d_in[14];

    float* out    = (float*)d_out;
    float* qc_out = out;                  // (B,3,256)
    float* qf_out = out + B*3*N2;         // (B,128,256)

    const int smemD = (64*68  + 4*16*32 + 4*32) * 4;   // 26112 B
    const int smemF = (64*132 + 4*16*64 + 4*64) * 4;   // 51200 B
    const int smemH = (128*132 + 2*16*64 + 2*64) * 4;  // 76288 B
    cudaFuncSetAttribute(kernelF, cudaFuncAttributeMaxDynamicSharedMemorySize, smemF);
    cudaFuncSetAttribute(kernelH, cudaFuncAttributeMaxDynamicSharedMemorySize, smemH);

    kernelA<<<69, 512>>>(pc, Wt, bt);                  // fps1+fps2 (dual) || knn1+feat || zero
    kernelB<<<4192, 256>>>(pc, W1);                    // edge1 || gather qc1
    kernelC<<<4200, 256>>>(pc, g1, b1);                // knn2split||knn3||knn4||finalize1
    kernelD<<<2048, 256, smemD>>>(W2);                 // edge2
    kernelE<<<2048, 256>>>(g2, b2);                    // finalize2 -> qf2
    kernelF<<<2048, 256, smemF>>>(W3);                 // edge3
    kernelG<<<2072, 256>>>(g3, b3, qc_out);            // finalize3 -> kf3 || qc_out
    kernelH<<<1024, 256, smemH>>>(W4);                 // edge4
    kernelI<<<1024, 256>>>(g4, b4, qf_out);            // finalize4 -> qf_out
}

// round 13
// speedup vs baseline: 1.0031x; 1.0031x over previous
#include <cuda_runtime.h>
#include <math.h>
#include <stdint.h>

#define FULLMASK 0xffffffffu

static const int B  = 8;
static const int N0 = 4096;
static const int N1 = 1024;
static const int N2 = 256;

// ---------------- scratch (device globals) ----------------------------------
__device__ float d_feat0[B*N0*8];      // (B,N0,8)  channels-last
__device__ float d_kf1  [B*N0*32];     // (B,N0,32) channels-last
__device__ float d_qc1  [B*3*N1];      // (B,3,N1)  channels-first
__device__ float d_qf2  [B*N1*64];     // (B,N1,64)
__device__ float d_kf3  [B*N1*64];     // (B,N1,64)
__device__ float d_hmax [B*N0*32];     // per-(b,q,o) max_k h (reused per layer)
__device__ float d_hmin [B*N0*32];
__device__ int   d_nidx [B*N0*16];     // knn layer1/2 indices
__device__ int   d_nidx2[B*N1*16];     // knn layer3
__device__ int   d_nidx3[B*N2*16];     // knn layer4
__device__ int   d_fidx [B*N1];        // fps1 indices
__device__ int   d_fidx2[B*N2];        // fps2 indices (local into N1 subset)
__device__ float d_gsum [4*B*4];
__device__ float d_gsq  [4*B*4];

// ---------------- warp redux / barrier helpers --------------------------------
__device__ __forceinline__ unsigned redux_max_u32(unsigned v) {
    unsigned r; asm("redux.sync.max.u32 %0, %1, 0xffffffff;" : "=r"(r) : "r"(v)); return r;
}
__device__ __forceinline__ unsigned redux_min_u32(unsigned v) {
    unsigned r; asm("redux.sync.min.u32 %0, %1, 0xffffffff;" : "=r"(r) : "r"(v)); return r;
}
__device__ __forceinline__ void bar_named(int id) {
    asm volatile("bar.sync %0, 256;" :: "r"(id) : "memory");
}

// ---------------- packed f32x2 helpers ----------------------------------------
__device__ __forceinline__ unsigned long long pack2(float lo, float hi) {
    unsigned long long v;
    asm("mov.b64 %0, {%1, %2};" : "=l"(v) : "f"(lo), "f"(hi));
    return v;
}
// d = ((x-lx)^2 + (y-ly)^2) + (z-lz)^2 for two points, per-lane rn arithmetic
// (add of negated value == sub, mul/add rounding identical to scalar path).
__device__ __forceinline__ void dist2_pair(
    unsigned long long px2, unsigned long long py2, unsigned long long pz2,
    unsigned long long nlx2, unsigned long long nly2, unsigned long long nlz2,
    float& d0, float& d1)
{
    unsigned long long dx, dy, dz, s;
    asm("add.rn.f32x2 %0, %1, %2;" : "=l"(dx) : "l"(px2), "l"(nlx2));
    asm("add.rn.f32x2 %0, %1, %2;" : "=l"(dy) : "l"(py2), "l"(nly2));
    asm("add.rn.f32x2 %0, %1, %2;" : "=l"(dz) : "l"(pz2), "l"(nlz2));
    asm("mul.rn.f32x2 %0, %1, %1;" : "=l"(dx) : "l"(dx));
    asm("mul.rn.f32x2 %0, %1, %1;" : "=l"(dy) : "l"(dy));
    asm("mul.rn.f32x2 %0, %1, %1;" : "=l"(dz) : "l"(dz));
    asm("add.rn.f32x2 %0, %1, %2;" : "=l"(s)  : "l"(dx), "l"(dy));
    asm("add.rn.f32x2 %0, %1, %2;" : "=l"(s)  : "l"(s),  "l"(dz));
    asm("mov.b64 {%0, %1}, %2;" : "=f"(d0), "=f"(d1) : "l"(s));
}

// thread-local argmax over dd[NPT]: max via FMNMX tree, then min encoded index
// among exact-equal values (matches scan-order tie-break).
template<int NPT>
__device__ __forceinline__ void fps_argmax(const float* dd, int t, float& bv, int& bi)
{
    float m[NPT];
    #pragma unroll
    for (int p = 0; p < NPT; p++) m[p] = dd[p];
    #pragma unroll
    for (int s = NPT/2; s > 0; s >>= 1)
        #pragma unroll
        for (int p = 0; p < s; p++) m[p] = fmaxf(m[p], m[p+s]);
    bv = m[0];
    int enc[NPT];
    #pragma unroll
    for (int p = 0; p < NPT; p++)
        enc[p] = (dd[p] == bv) ? (t + (p << 8)) : 0x7FFFFFFF;
    #pragma unroll
    for (int s = NPT/2; s > 0; s >>= 1)
        #pragma unroll
        for (int p = 0; p < s; p++) enc[p] = min(enc[p], enc[p+s]);
    bi = enc[0];
}

// post-barrier 8-slot winner: pairwise u64 tree (depth 3)
__device__ __forceinline__ int fps_block_winner(const unsigned long long* slot)
{
    unsigned long long v0 = slot[0], v1 = slot[1], v2 = slot[2], v3 = slot[3];
    unsigned long long v4 = slot[4], v5 = slot[5], v6 = slot[6], v7 = slot[7];
    unsigned long long a = (v0 > v1) ? v0 : v1;
    unsigned long long b = (v2 > v3) ? v2 : v3;
    unsigned long long c = (v4 > v5) ? v4 : v5;
    unsigned long long d = (v6 > v7) ? v6 : v7;
    a = (a > b) ? a : b;
    c = (c > d) ? c : d;
    a = (a > c) ? a : c;
    return (int)(~(unsigned)a);
}

// ---------------- dual-FPS: one 256-thread group does fps1 then fps2 ----------
// Group g of the block handles batch b. Named barrier (1+g) syncs the group.
// Selected coords stashed in s_sel (3*N1 floats) during fps1; fps2 runs on them.
__device__ void fps_dual(const float* __restrict__ pc, int b, int g,
                         float* s_sel, unsigned long long* s_win,
                         int* __restrict__ outidx1, int* __restrict__ outidx2)
{
    const int t = threadIdx.x & 255;
    const int barid = 1 + g;
    float* s_sx = s_sel;
    float* s_sy = s_sel + N1;
    float* s_sz = s_sel + 2*N1;
    const float* cx = pc + (b*3+0)*N0;
    const float* cy = pc + (b*3+1)*N0;
    const float* cz = pc + (b*3+2)*N0;

    // ---- fps1: 4096 -> 1024, 16 pts/thread ----
    {
        unsigned long long px2[8], py2[8], pz2[8];
        float dd[16];
        #pragma unroll
        for (int p = 0; p < 8; p++) {
            int i0 = t + ((2*p)   << 8);
            int i1 = t + ((2*p+1) << 8);
            px2[p] = pack2(cx[i0], cx[i1]);
            py2[p] = pack2(cy[i0], cy[i1]);
            pz2[p] = pack2(cz[i0], cz[i1]);
            dd[2*p] = 1e10f; dd[2*p+1] = 1e10f;
        }
        float lx = cx[0], ly = cy[0], lz = cz[0];
        if (t == 0) {
            outidx1[b*N1] = 0;
            s_sx[0] = lx; s_sy[0] = ly; s_sz[0] = lz;
        }
        for (int it = 1; it < N1; ++it) {
            unsigned long long nlx2 = pack2(-lx, -lx);
            unsigned long long nly2 = pack2(-ly, -ly);
            unsigned long long nlz2 = pack2(-lz, -lz);
            #pragma unroll
            for (int p = 0; p < 8; p++) {
                float d0, d1;
                dist2_pair(px2[p], py2[p], pz2[p], nlx2, nly2, nlz2, d0, d1);
                dd[2*p]   = fminf(dd[2*p],   d0);
                dd[2*p+1] = fminf(dd[2*p+1], d1);
            }
            float bv; int bi;
            fps_argmax<16>(dd, t, bv, bi);
            unsigned db = __float_as_uint(bv);
            unsigned m  = redux_max_u32(db);
            unsigned mi = redux_min_u32(db == m ? (unsigned)bi : 0xFFFFFFFFu);
            int cur = it & 1;
            if ((t & 31) == 0)
                s_win[cur*8 + (t >> 5)] = ((unsigned long long)m << 32) | (unsigned)(~mi);
            bar_named(barid);
            int sel = fps_block_winner(&s_win[cur*8]);
            if (t == 0) outidx1[b*N1 + it] = sel;
            lx = cx[sel]; ly = cy[sel]; lz = cz[sel];
            if (t == 0) { s_sx[it] = lx; s_sy[it] = ly; s_sz[it] = lz; }
        }
    }
    bar_named(barid);   // make s_sel visible to the group

    // ---- fps2: 1024 -> 256 on stashed coords, 4 pts/thread ----
    {
        unsigned long long px2[2], py2[2], pz2[2];
        float dd[4];
        #pragma unroll
        for (int p = 0; p < 2; p++) {
            int i0 = t + ((2*p)   << 8);
            int i1 = t + ((2*p+1) << 8);
            px2[p] = pack2(s_sx[i0], s_sx[i1]);
            py2[p] = pack2(s_sy[i0], s_sy[i1]);
            pz2[p] = pack2(s_sz[i0], s_sz[i1]);
            dd[2*p] = 1e10f; dd[2*p+1] = 1e10f;
        }
        float lx = s_sx[0], ly = s_sy[0], lz = s_sz[0];
        if (t == 0) outidx2[b*N2] = 0;
        for (int it = 1; it < N2; ++it) {
            unsigned long long nlx2 = pack2(-lx, -lx);
            unsigned long long nly2 = pack2(-ly, -ly);
            unsigned long long nlz2 = pack2(-lz, -lz);
            #pragma unroll
            for (int p = 0; p < 2; p++) {
                float d0, d1;
                dist2_pair(px2[p], py2[p], pz2[p], nlx2, nly2, nlz2, d0, d1);
                dd[2*p]   = fminf(dd[2*p],   d0);
                dd[2*p+1] = fminf(dd[2*p+1], d1);
            }
            float bv; int bi;
            fps_argmax<4>(dd, t, bv, bi);
            unsigned db = __float_as_uint(bv);
            unsigned m  = redux_max_u32(db);
            unsigned mi = redux_min_u32(db == m ? (unsigned)bi : 0xFFFFFFFFu);
            int cur = it & 1;
            if ((t & 31) == 0)
                s_win[cur*8 + (t >> 5)] = ((unsigned long long)m << 32) | (unsigned)(~mi);
            bar_named(barid);
            int sel = fps_block_winner(&s_win[cur*8]);
            if (t == 0) outidx2[b*N2 + it] = sel;
            lx = s_sx[sel]; ly = s_sy[sel]; lz = s_sz[sel];
        }
    }
}

// ---------------- KNN: BT queries/block, optional indirection + feat ---------
template<int BT>
__device__ void knn_block(const float* __restrict__ qcoord, int qstride, const int* __restrict__ qidxmap,
                          const float* __restrict__ kcoord, int kstride, const int* __restrict__ kidxmap,
                          int Q, int Kn, int b, int qtile, int* __restrict__ nidx,
                          const int* __restrict__ omap,
                          bool dofeat, const float* __restrict__ Wt, const float* __restrict__ bt,
                          float* __restrict__ feat0)
{
    __shared__ float4 sk[BT];
    const int tid = threadIdx.x;
    int q = qtile*BT + tid;
    int qr = qidxmap ? qidxmap[b*Q + q] : q;
    float x = qcoord[(b*3+0)*qstride + qr];
    float y = qcoord[(b*3+1)*qstride + qr];
    float z = qcoord[(b*3+2)*qstride + qr];
    if (dofeat) {
        float f[8];
        #pragma unroll
        for (int o = 0; o < 8; o++)
            f[o] = fmaf(Wt[o*3+2], z, fmaf(Wt[o*3+1], y, fmaf(Wt[o*3+0], x, bt[o])));
        float4* dst = (float4*)&feat0[((size_t)(b*N0 + q))*8];
        dst[0] = make_float4(f[0], f[1], f[2], f[3]);
        dst[1] = make_float4(f[4], f[5], f[6], f[7]);
    }
    float q2 = __fadd_rn(__fadd_rn(__fmul_rn(x,x), __fmul_rn(y,y)), __fmul_rn(z,z));
    float bd[16]; int bi[16];
    #pragma unroll
    for (int r = 0; r < 16; r++) { bd[r] = 3.4e38f; bi[r] = 0; }
    for (int t0 = 0; t0 < Kn; t0 += BT) {
        int j  = t0 + tid;
        int kr = kidxmap ? kidxmap[b*Kn + j] : j;
        float kx = kcoord[(b*3+0)*kstride + kr];
        float ky = kcoord[(b*3+1)*kstride + kr];
        float kz = kcoord[(b*3+2)*kstride + kr];
        float k2 = __fadd_rn(__fadd_rn(__fmul_rn(kx,kx), __fmul_rn(ky,ky)), __fmul_rn(kz,kz));
        __syncthreads();
        sk[tid] = make_float4(kx, ky, kz, k2);
        __syncthreads();
        #pragma unroll 4
        for (int kk = 0; kk < BT; kk++) {
            float4 s  = sk[kk];
            float dot = __fadd_rn(__fadd_rn(__fmul_rn(x,s.x), __fmul_rn(y,s.y)), __fmul_rn(z,s.z));
            float d2  = __fsub_rn(__fadd_rn(q2, s.w), __fmul_rn(2.0f, dot));
            if (d2 < bd[15]) {
                bd[15] = d2; bi[15] = t0 + kk;
                #pragma unroll
                for (int r = 15; r > 0; --r) {
                    if (bd[r] < bd[r-1]) {
                        float td = bd[r]; bd[r] = bd[r-1]; bd[r-1] = td;
                        int   ti = bi[r]; bi[r] = bi[r-1]; bi[r-1] = ti;
                    }
                }
            }
        }
    }
    #pragma unroll
    for (int r = 0; r < 16; r++) {
        int v = bi[r];
        nidx[((size_t)(b*Q + q))*16 + r] = omap ? omap[b*Kn + v] : v;
    }
}

// ---------------- KNN split: 128 queries/block, 2 threads/query (key halves) --
__device__ void knn_split_block(const float* __restrict__ qc, const float* __restrict__ kc,
                                int b, int qtile, int* __restrict__ nidx)
{
    __shared__ float4 skk[512];
    __shared__ unsigned long long s_k[128][32];
    const int tid  = threadIdx.x;
    const int ql   = tid & 127;
    const int half = tid >> 7;
    int q = qtile*128 + ql;
    float x = qc[(b*3+0)*N1 + q];
    float y = qc[(b*3+1)*N1 + q];
    float z = qc[(b*3+2)*N1 + q];
    float q2 = __fadd_rn(__fadd_rn(__fmul_rn(x,x), __fmul_rn(y,y)), __fmul_rn(z,z));
    float bd[16]; int bi[16];
    #pragma unroll
    for (int r = 0; r < 16; r++) { bd[r] = 3.4e38f; bi[r] = 0; }
    const int kbase = half*2048;
    for (int t0 = 0; t0 < 2048; t0 += 256) {
        {
            int j0 = t0 + tid;
            float kx = kc[(b*3+0)*N0 + j0];
            float ky = kc[(b*3+1)*N0 + j0];
            float kz = kc[(b*3+2)*N0 + j0];
            float k2 = __fadd_rn(__fadd_rn(__fmul_rn(kx,kx), __fmul_rn(ky,ky)), __fmul_rn(kz,kz));
            int j1 = 2048 + t0 + tid;
            float kx1 = kc[(b*3+0)*N0 + j1];
            float ky1 = kc[(b*3+1)*N0 + j1];
            float kz1 = kc[(b*3+2)*N0 + j1];
            float k21 = __fadd_rn(__fadd_rn(__fmul_rn(kx1,kx1), __fmul_rn(ky1,ky1)), __fmul_rn(kz1,kz1));
            __syncthreads();
            skk[tid]       = make_float4(kx,  ky,  kz,  k2);
            skk[256 + tid] = make_float4(kx1, ky1, kz1, k21);
            __syncthreads();
        }
        const float4* sh = skk + half*256;
        #pragma unroll 4
        for (int kk = 0; kk < 256; kk++) {
            float4 s  = sh[kk];
            float dot = __fadd_rn(__fadd_rn(__fmul_rn(x,s.x), __fmul_rn(y,s.y)), __fmul_rn(z,s.z));
            float d2  = __fsub_rn(__fadd_rn(q2, s.w), __fmul_rn(2.0f, dot));
            if (d2 < bd[15]) {
                bd[15] = d2; bi[15] = kbase + t0 + kk;
                #pragma unroll
                for (int r = 15; r > 0; --r) {
                    if (bd[r] < bd[r-1]) {
                        float td = bd[r]; bd[r] = bd[r-1]; bd[r-1] = td;
                        int   ti = bi[r]; bi[r] = bi[r-1]; bi[r-1] = ti;
                    }
                }
            }
        }
    }
    #pragma unroll
    for (int r = 0; r < 16; r++) {
        unsigned dbits = __float_as_uint(bd[r]);
        dbits = (dbits & 0x80000000u) ? ~dbits : (dbits ^ 0x80000000u);   // total order
        s_k[ql][half*16 + r] = ((unsigned long long)dbits << 32) | (unsigned)bi[r];
    }
    __syncthreads();
    if (half == 0) {
        int ia = 0, ib = 0;
        #pragma unroll
        for (int r = 0; r < 16; r++) {
            unsigned long long ka = s_k[ql][min(ia,15)];
            unsigned long long kb = s_k[ql][16 + min(ib,15)];
            bool ta = (ib >= 16) || ((ia < 16) && (ka <= kb));  // tie -> half0 (lower idx)
            unsigned idx = (unsigned)(ta ? ka : kb);
            nidx[((size_t)(b*N1 + q))*16 + r] = (int)idx;
            ia += ta ? 1 : 0; ib += ta ? 0 : 1;
        }
    }
}

// ---------------- edge conv: shared-staged W, h in regs, hmax/hmin + stats ---
template<int CIN, int COUT, int QB>
__device__ void edge_block(float* sws, int eb,
                           const float* __restrict__ qf, int qrows, const int* __restrict__ qmap,
                           const float* __restrict__ kf, int Kn, const int* __restrict__ nidx,
                           const float* __restrict__ W,
                           float* __restrict__ hmax_o, float* __restrict__ hmin_o,
                           float* __restrict__ gsum, float* __restrict__ gsq, int Q)
{
    const int STR = 2*CIN + 4;
    const int NF4 = 2*CIN/4;
    float* s_W  = sws;
    float* s_nb = s_W + COUT*STR;
    float* s_qe = s_nb + QB*16*CIN;
    __shared__ float s_gs[4], s_gq[4];
    const int tid = threadIdx.x;
    const int b  = eb / (Q/QB);
    const int q0 = (eb % (Q/QB)) * QB;
    if (tid < 4) { s_gs[tid] = 0.f; s_gq[tid] = 0.f; }
    for (int i = tid; i < COUT*NF4; i += 256) {
        int o = i / NF4, j = i % NF4;
        *(float4*)&s_W[o*STR + j*4] = ((const float4*)W)[i];
    }
    for (int i = tid; i < QB*(CIN/4); i += 256) {
        int ql = i / (CIN/4), c4 = i % (CIN/4);
        int row = qmap ? qmap[b*Q + q0 + ql] : (q0 + ql);
        float4 v = *(const float4*)&qf[((size_t)b*qrows + row)*CIN + c4*4];
        *(float4*)&s_qe[ql*CIN + c4*4] = v;
    }
    for (int i = tid; i < QB*16*(CIN/4); i += 256) {
        int c4 = i % (CIN/4); int r = i / (CIN/4); int k = r & 15; int ql = r >> 4;
        int nb = nidx[((size_t)(b*Q + q0 + ql))*16 + k];
        float4 v = *(const float4*)&kf[((size_t)(b*Kn) + nb)*CIN + c4*4];
        *(float4*)&s_nb[(ql*16 + k)*CIN + c4*4] = v;
    }
    __syncthreads();
    const int ql = tid / COUT;
    const int o  = tid % COUT;
    float acc[16];
    #pragma unroll
    for (int k = 0; k < 16; k++) acc[k] = 0.f;
    float base = 0.f;
    const float* Wr  = s_W + o*STR;
    const float* qe_ = s_qe + ql*CIN;
    const float* nb_ = s_nb + ql*16*CIN;
    #pragma unroll
    for (int cc = 0; cc < CIN; cc += 4) {
        float4 w  = *(const float4*)&Wr[cc];
        float4 w2 = *(const float4*)&Wr[CIN + cc];
        float4 qe = *(const float4*)&qe_[cc];
        base = fmaf(w2.x - w.x, qe.x, base);
        base = fmaf(w2.y - w.y, qe.y, base);
        base = fmaf(w2.z - w.z, qe.z, base);
        base = fmaf(w2.w - w.w, qe.w, base);
        #pragma unroll
        for (int k = 0; k < 16; k++) {
            float4 nb4 = *(const float4*)&nb_[k*CIN + cc];
            acc[k] = fmaf(w.x, nb4.x, acc[k]);
            acc[k] = fmaf(w.y, nb4.y, acc[k]);
            acc[k] = fmaf(w.z, nb4.z, acc[k]);
            acc[k] = fmaf(w.w, nb4.w, acc[k]);
        }
    }
    float hmx = -3.4e38f, hmn = 3.4e38f, s = 0.f, sq = 0.f;
    #pragma unroll
    for (int k = 0; k < 16; k++) {
        float h = base + acc[k];
        hmx = fmaxf(hmx, h); hmn = fminf(hmn, h);
        s += h; sq = fmaf(h, h, sq);
    }
    const int width = (COUT/4 < 32) ? (COUT/4) : 32;
    #pragma unroll
    for (int off = width >> 1; off; off >>= 1) {
        s  += __shfl_down_sync(FULLMASK, s,  off, width);
        sq += __shfl_down_sync(FULLMASK, sq, off, width);
    }
    int g = o / (COUT/4);
    if ((o & (width-1)) == 0) { atomicAdd(&s_gs[g], s); atomicAdd(&s_gq[g], sq); }
    size_t ofs = ((size_t)(b*Q + q0 + ql))*COUT + o;
    hmax_o[ofs] = hmx; hmin_o[ofs] = hmn;
    __syncthreads();
    if (tid < 4) { atomicAdd(&gsum[b*4+tid], s_gs[tid]); atomicAdd(&gsq[b*4+tid], s_gq[tid]); }
}

// ---------------- finalize: y = leaky(hext*sc + sh) ---------------------------
__device__ void finalize_elem(int lin, const float* __restrict__ hmax, const float* __restrict__ hmin,
                              const float* __restrict__ gsum, const float* __restrict__ gsq,
                              const float* __restrict__ gamma, const float* __restrict__ beta,
                              float* __restrict__ out, int Q, int COUT, float inv_n, bool cf)
{
    int o = lin % COUT; int t = lin / COUT; int q = t % Q; int b = t / Q;
    int g = o / (COUT/4);
    float mean = gsum[b*4+g] * inv_n;
    float var  = gsq [b*4+g] * inv_n - mean*mean;
    float inv  = 1.0f / sqrtf(var + 1e-5f);
    float sc = gamma[o] * inv;
    float sh = beta[o] - mean * sc;
    float hv = (sc >= 0.f) ? hmax[lin] : hmin[lin];
    float yv = hv*sc + sh;
    yv = (yv >= 0.f) ? yv : 0.2f*yv;
    if (cf) out[(b*COUT + o)*Q + q] = yv;
    else    out[lin] = yv;
}

// ---------------- megakernels --------------------------------------------------
// blocks 0-3: dual fps (2 batches each, named-barrier groups); 4-67: knn1 (512t);
// 68: zero stats
__global__ void __launch_bounds__(512) kernelA(const float* __restrict__ pc,
                                               const float* __restrict__ Wt,
                                               const float* __restrict__ bt)
{
    __shared__ float s_sel[2][3*N1];
    __shared__ unsigned long long s_win[2][16];
    int blk = blockIdx.x;
    if (blk < 4) {
        int g = threadIdx.x >> 8;           // group 0/1
        int b = blk + 4*g;                  // batches 0-3 / 4-7
        fps_dual(pc, b, g, s_sel[g], s_win[g], d_fidx, d_fidx2);
    } else if (blk < 68) {
        int r = blk - 4;
        knn_block<512>(pc, N0, nullptr, pc, N0, nullptr, N0, N0, r/8, r%8,
                       d_nidx, nullptr, true, Wt, bt, d_feat0);
    } else {
        int t = threadIdx.x;
        if (t < 128) { d_gsum[t] = 0.f; d_gsq[t] = 0.f; }
    }
}

// edge1 || gather qc1
__global__ void __launch_bounds__(256) kernelB(const float* __restrict__ pc,
                                               const float* __restrict__ W1)
{
    __shared__ float ews[32*20 + 8*16*8 + 8*8];   // edge1 workspace (1728 floats)
    int blk = blockIdx.x;
    if (blk < 4096) {
        edge_block<8,32,8>(ews, blk, d_feat0, N0, nullptr, d_feat0, N0, d_nidx, W1,
                           d_hmax, d_hmin, d_gsum + 0, d_gsq + 0, N0);
    } else {
        int lin = (blk - 4096)*256 + threadIdx.x;      // B*3*N1 = 24576
        int j = lin % N1; int c = (lin/N1) % 3; int b = lin/(3*N1);
        d_qc1[lin] = pc[(b*3+c)*N0 + d_fidx[b*N1 + j]];
    }
}

// knn2(split) || knn3 || knn4 || finalize1
__global__ void __launch_bounds__(256) kernelC(const float* __restrict__ pc,
                                               const float* __restrict__ g1,
                                               const float* __restrict__ b1)
{
    int blk = blockIdx.x;
    if (blk < 64) {
        knn_split_block(d_qc1, pc, blk/8, blk%8, d_nidx);
    } else if (blk < 96) {
        int r = blk - 64;
        knn_block<256>(d_qc1, N1, nullptr, d_qc1, N1, nullptr, N1, N1, r/4, r%4,
                       d_nidx2, nullptr, false, nullptr, nullptr, nullptr);
    } else if (blk < 104) {
        knn_block<256>(d_qc1, N1, d_fidx2, d_qc1, N1, d_fidx2, N2, N2, blk - 96, 0,
                       d_nidx3, d_fidx2, false, nullptr, nullptr, nullptr);
    } else {
        int lin = (blk - 104)*256 + threadIdx.x;       // B*N0*32
        finalize_elem(lin, d_hmax, d_hmin, d_gsum + 0, d_gsq + 0, g1, b1,
                      d_kf1, N0, 32, 1.0f/(8.0f*N0*16.0f), false);
    }
}

__global__ void __launch_bounds__(256) kernelD(const float* __restrict__ W2)
{
    extern __shared__ float dsm[];
    edge_block<32,64,4>(dsm, blockIdx.x, d_kf1, N0, d_fidx, d_kf1, N0, d_nidx, W2,
                        d_hmax, d_hmin, d_gsum + 32, d_gsq + 32, N1);
}

__global__ void __launch_bounds__(256) kernelE(const float* __restrict__ g2,
                                               const float* __restrict__ b2)
{
    int lin = blockIdx.x*256 + threadIdx.x;            // B*N1*64
    finalize_elem(lin, d_hmax, d_hmin, d_gsum + 32, d_gsq + 32, g2, b2,
                  d_qf2, N1, 64, 1.0f/(16.0f*N1*16.0f), false);
}

__global__ void __launch_bounds__(256) kernelF(const float* __restrict__ W3)
{
    extern __shared__ float dsm[];
    edge_block<64,64,4>(dsm, blockIdx.x, d_qf2, N1, nullptr, d_qf2, N1, d_nidx2, W3,
                        d_hmax, d_hmin, d_gsum + 64, d_gsq + 64, N1);
}

__global__ void __launch_bounds__(256) kernelG(const float* __restrict__ g3,
                                               const float* __restrict__ b3,
                                               float* __restrict__ qc_out)
{
    int blk = blockIdx.x;
    if (blk < 2048) {
        int lin = blk*256 + threadIdx.x;               // B*N1*64
        finalize_elem(lin, d_hmax, d_hmin, d_gsum + 64, d_gsq + 64, g3, b3,
                      d_kf3, N1, 64, 1.0f/(16.0f*N1*16.0f), false);
    } else {
        int lin = (blk - 2048)*256 + threadIdx.x;      // B*3*N2 = 6144
        int j = lin % N2; int c = (lin/N2) % 3; int b = lin/(3*N2);
        qc_out[lin] = d_qc1[(b*3+c)*N1 + d_fidx2[b*N2 + j]];
    }
}

__global__ void __launch_bounds__(256) kernelH(const float* __restrict__ W4)
{
    extern __shared__ float dsm[];
    edge_block<64,128,2>(dsm, blockIdx.x, d_kf3, N1, d_fidx2, d_kf3, N1, d_nidx3, W4,
                         d_hmax, d_hmin, d_gsum + 96, d_gsq + 96, N2);
}

__global__ void __launch_bounds__(256) kernelI(const float* __restrict__ g4,
                                               const float* __restrict__ b4,
                                               float* __restrict__ qf_out)
{
    int lin = blockIdx.x*256 + threadIdx.x;            // B*N2*128
    finalize_elem(lin, d_hmax, d_hmin, d_gsum + 96, d_gsq + 96, g4, b4,
                  qf_out, N2, 128, 1.0f/(32.0f*N2*16.0f), true);
}

// ---------------- launch --------------------------------------------------------
extern "C" void kernel_launch(void* const* d_in, const int* in_sizes, int n_in,
                              void* d_out, int out_size) {
    const float* pc = (const float*)d_in[0];
    const float* Wt = (const float*)d_in[1];
    const float* bt = (const float*)d_in[2];
    const float* W1 = (const float*)d_in[3];
    const float* g1 = (const float*)d_in[4];
    const float* b1 = (const float*)d_in[5];
    const float* W2 = (const float*)d_in[6];
    const float* g2 = (const float*)d_in[7];
    const float* b2 = (const float*)d_in[8];
    const float* W3 = (const float*)d_in[9];
    const float* g3 = (const float*)d_in[10];
    const float* b3 = (const float*)d_in[11];
    const float* W4 = (const float*)d_in[12];
    const float* g4 = (const float*)d_in[13];
    const float* b4 = (const float*)d_in[14];

    float* out    = (float*)d_out;
    float* qc_out = out;                  // (B,3,256)
    float* qf_out = out + B*3*N2;         // (B,128,256)

    const int smemD = (64*68  + 4*16*32 + 4*32) * 4;   // 26112 B
    const int smemF = (64*132 + 4*16*64 + 4*64) * 4;   // 51200 B
    const int smemH = (128*132 + 2*16*64 + 2*64) * 4;  // 76288 B
    cudaFuncSetAttribute(kernelF, cudaFuncAttributeMaxDynamicSharedMemorySize, smemF);
    cudaFuncSetAttribute(kernelH, cudaFuncAttributeMaxDynamicSharedMemorySize, smemH);

    kernelA<<<69, 512>>>(pc, Wt, bt);                  // fps1+fps2 (dual) || knn1+feat || zero
    kernelB<<<4192, 256>>>(pc, W1);                    // edge1 || gather qc1
    kernelC<<<4200, 256>>>(pc, g1, b1);                // knn2split||knn3||knn4||finalize1
    kernelD<<<2048, 256, smemD>>>(W2);                 // edge2
    kernelE<<<2048, 256>>>(g2, b2);                    // finalize2 -> qf2
    kernelF<<<2048, 256, smemF>>>(W3);                 // edge3
    kernelG<<<2072, 256>>>(g3, b3, qc_out);            // finalize3 -> kf3 || qc_out
    kernelH<<<1024, 256, smemH>>>(W4);                 // edge4
    kernelI<<<1024, 256>>>(g4, b4, qf_out);            // finalize4 -> qf_out
}

// round 14
// speedup vs baseline: 1.0038x; 1.0006x over previous
#include <cuda_runtime.h>
#include <math.h>
#include <stdint.h>

#define FULLMASK 0xffffffffu

static const int B  = 8;
static const int N0 = 4096;
static const int N1 = 1024;
static const int N2 = 256;

// ---------------- scratch (device globals) ----------------------------------
__device__ float d_feat0[B*N0*8];      // (B,N0,8)  channels-last
__device__ float d_kf1  [B*N0*32];     // (B,N0,32) channels-last
__device__ float d_qc1  [B*3*N1];      // (B,3,N1)  channels-first
__device__ float d_qf2  [B*N1*64];     // (B,N1,64)
__device__ float d_kf3  [B*N1*64];     // (B,N1,64)
__device__ float d_hmax [B*N0*32];     // per-(b,q,o) max_k h (reused per layer)
__device__ float d_hmin [B*N0*32];
__device__ int   d_nidx [B*N0*16];     // knn layer1/2 indices
__device__ int   d_nidx2[B*N1*16];     // knn layer3
__device__ int   d_nidx3[B*N2*16];     // knn layer4
__device__ int   d_fidx [B*N1];        // fps1 indices
__device__ int   d_fidx2[B*N2];        // fps2 indices (local into N1 subset)
__device__ float d_gsum [4*B*4];
__device__ float d_gsq  [4*B*4];

// ---------------- warp redux / barrier helpers --------------------------------
__device__ __forceinline__ unsigned redux_max_u32(unsigned v) {
    unsigned r; asm("redux.sync.max.u32 %0, %1, 0xffffffff;" : "=r"(r) : "r"(v)); return r;
}
__device__ __forceinline__ unsigned redux_min_u32(unsigned v) {
    unsigned r; asm("redux.sync.min.u32 %0, %1, 0xffffffff;" : "=r"(r) : "r"(v)); return r;
}
__device__ __forceinline__ void bar_named(int id) {
    asm volatile("bar.sync %0, 256;" :: "r"(id) : "memory");
}

// ---------------- packed f32x2 helpers ----------------------------------------
__device__ __forceinline__ unsigned long long pack2(float lo, float hi) {
    unsigned long long v;
    asm("mov.b64 %0, {%1, %2};" : "=l"(v) : "f"(lo), "f"(hi));
    return v;
}
// d = ((x-lx)^2 + (y-ly)^2) + (z-lz)^2 for two points, per-lane rn arithmetic
// (add of negated value == sub, mul/add rounding identical to scalar path).
__device__ __forceinline__ void dist2_pair(
    unsigned long long px2, unsigned long long py2, unsigned long long pz2,
    unsigned long long nlx2, unsigned long long nly2, unsigned long long nlz2,
    float& d0, float& d1)
{
    unsigned long long dx, dy, dz, s;
    asm("add.rn.f32x2 %0, %1, %2;" : "=l"(dx) : "l"(px2), "l"(nlx2));
    asm("add.rn.f32x2 %0, %1, %2;" : "=l"(dy) : "l"(py2), "l"(nly2));
    asm("add.rn.f32x2 %0, %1, %2;" : "=l"(dz) : "l"(pz2), "l"(nlz2));
    asm("mul.rn.f32x2 %0, %1, %1;" : "=l"(dx) : "l"(dx));
    asm("mul.rn.f32x2 %0, %1, %1;" : "=l"(dy) : "l"(dy));
    asm("mul.rn.f32x2 %0, %1, %1;" : "=l"(dz) : "l"(dz));
    asm("add.rn.f32x2 %0, %1, %2;" : "=l"(s)  : "l"(dx), "l"(dy));
    asm("add.rn.f32x2 %0, %1, %2;" : "=l"(s)  : "l"(s),  "l"(dz));
    asm("mov.b64 {%0, %1}, %2;" : "=f"(d0), "=f"(d1) : "l"(s));
}

// thread-local argmax over dd[NPT]: max via FMNMX tree, then min encoded index
// among exact-equal values (matches scan-order tie-break).
template<int NPT>
__device__ __forceinline__ void fps_argmax(const float* dd, int t, float& bv, int& bi)
{
    float m[NPT];
    #pragma unroll
    for (int p = 0; p < NPT; p++) m[p] = dd[p];
    #pragma unroll
    for (int s = NPT/2; s > 0; s >>= 1)
        #pragma unroll
        for (int p = 0; p < s; p++) m[p] = fmaxf(m[p], m[p+s]);
    bv = m[0];
    int enc[NPT];
    #pragma unroll
    for (int p = 0; p < NPT; p++)
        enc[p] = (dd[p] == bv) ? (t + (p << 8)) : 0x7FFFFFFF;
    #pragma unroll
    for (int s = NPT/2; s > 0; s >>= 1)
        #pragma unroll
        for (int p = 0; p < s; p++) enc[p] = min(enc[p], enc[p+s]);
    bi = enc[0];
}

// post-barrier 8-slot winner: pairwise u64 tree (depth 3)
__device__ __forceinline__ int fps_block_winner(const unsigned long long* slot)
{
    unsigned long long v0 = slot[0], v1 = slot[1], v2 = slot[2], v3 = slot[3];
    unsigned long long v4 = slot[4], v5 = slot[5], v6 = slot[6], v7 = slot[7];
    unsigned long long a = (v0 > v1) ? v0 : v1;
    unsigned long long b = (v2 > v3) ? v2 : v3;
    unsigned long long c = (v4 > v5) ? v4 : v5;
    unsigned long long d = (v6 > v7) ? v6 : v7;
    a = (a > b) ? a : b;
    c = (c > d) ? c : d;
    a = (a > c) ? a : c;
    return (int)(~(unsigned)a);
}

// ---------------- dual-FPS: one 256-thread group does fps1 then fps2 ----------
// Group g of the block handles batch b. Named barrier (1+g) syncs the group.
// Selected coords stashed in s_sel (3*N1 floats) during fps1; fps2 runs on them.
__device__ void fps_dual(const float* __restrict__ pc, int b, int g,
                         float* s_sel, unsigned long long* s_win,
                         int* __restrict__ outidx1, int* __restrict__ outidx2)
{
    const int t = threadIdx.x & 255;
    const int barid = 1 + g;
    float* s_sx = s_sel;
    float* s_sy = s_sel + N1;
    float* s_sz = s_sel + 2*N1;
    const float* cx = pc + (b*3+0)*N0;
    const float* cy = pc + (b*3+1)*N0;
    const float* cz = pc + (b*3+2)*N0;

    // ---- fps1: 4096 -> 1024, 16 pts/thread ----
    {
        unsigned long long px2[8], py2[8], pz2[8];
        float dd[16];
        #pragma unroll
        for (int p = 0; p < 8; p++) {
            int i0 = t + ((2*p)   << 8);
            int i1 = t + ((2*p+1) << 8);
            px2[p] = pack2(cx[i0], cx[i1]);
            py2[p] = pack2(cy[i0], cy[i1]);
            pz2[p] = pack2(cz[i0], cz[i1]);
            dd[2*p] = 1e10f; dd[2*p+1] = 1e10f;
        }
        float lx = cx[0], ly = cy[0], lz = cz[0];
        if (t == 0) {
            outidx1[b*N1] = 0;
            s_sx[0] = lx; s_sy[0] = ly; s_sz[0] = lz;
        }
        for (int it = 1; it < N1; ++it) {
            unsigned long long nlx2 = pack2(-lx, -lx);
            unsigned long long nly2 = pack2(-ly, -ly);
            unsigned long long nlz2 = pack2(-lz, -lz);
            #pragma unroll
            for (int p = 0; p < 8; p++) {
                float d0, d1;
                dist2_pair(px2[p], py2[p], pz2[p], nlx2, nly2, nlz2, d0, d1);
                dd[2*p]   = fminf(dd[2*p],   d0);
                dd[2*p+1] = fminf(dd[2*p+1], d1);
            }
            float bv; int bi;
            fps_argmax<16>(dd, t, bv, bi);
            unsigned db = __float_as_uint(bv);
            unsigned m  = redux_max_u32(db);
            unsigned mi = redux_min_u32(db == m ? (unsigned)bi : 0xFFFFFFFFu);
            int cur = it & 1;
            if ((t & 31) == 0)
                s_win[cur*8 + (t >> 5)] = ((unsigned long long)m << 32) | (unsigned)(~mi);
            bar_named(barid);
            int sel = fps_block_winner(&s_win[cur*8]);
            if (t == 0) outidx1[b*N1 + it] = sel;
            lx = cx[sel]; ly = cy[sel]; lz = cz[sel];
            if (t == 0) { s_sx[it] = lx; s_sy[it] = ly; s_sz[it] = lz; }
        }
    }
    bar_named(barid);   // make s_sel visible to the group

    // ---- fps2: 1024 -> 256 on stashed coords, 4 pts/thread ----
    {
        unsigned long long px2[2], py2[2], pz2[2];
        float dd[4];
        #pragma unroll
        for (int p = 0; p < 2; p++) {
            int i0 = t + ((2*p)   << 8);
            int i1 = t + ((2*p+1) << 8);
            px2[p] = pack2(s_sx[i0], s_sx[i1]);
            py2[p] = pack2(s_sy[i0], s_sy[i1]);
            pz2[p] = pack2(s_sz[i0], s_sz[i1]);
            dd[2*p] = 1e10f; dd[2*p+1] = 1e10f;
        }
        float lx = s_sx[0], ly = s_sy[0], lz = s_sz[0];
        if (t == 0) outidx2[b*N2] = 0;
        for (int it = 1; it < N2; ++it) {
            unsigned long long nlx2 = pack2(-lx, -lx);
            unsigned long long nly2 = pack2(-ly, -ly);
            unsigned long long nlz2 = pack2(-lz, -lz);
            #pragma unroll
            for (int p = 0; p < 2; p++) {
                float d0, d1;
                dist2_pair(px2[p], py2[p], pz2[p], nlx2, nly2, nlz2, d0, d1);
                dd[2*p]   = fminf(dd[2*p],   d0);
                dd[2*p+1] = fminf(dd[2*p+1], d1);
            }
            float bv; int bi;
            fps_argmax<4>(dd, t, bv, bi);
            unsigned db = __float_as_uint(bv);
            unsigned m  = redux_max_u32(db);
            unsigned mi = redux_min_u32(db == m ? (unsigned)bi : 0xFFFFFFFFu);
            int cur = it & 1;
            if ((t & 31) == 0)
                s_win[cur*8 + (t >> 5)] = ((unsigned long long)m << 32) | (unsigned)(~mi);
            bar_named(barid);
            int sel = fps_block_winner(&s_win[cur*8]);
            if (t == 0) outidx2[b*N2 + it] = sel;
            lx = s_sx[sel]; ly = s_sy[sel]; lz = s_sz[sel];
        }
    }
}

// ---------------- KNN: BT queries/block, optional indirection + feat ---------
template<int BT>
__device__ void knn_block(const float* __restrict__ qcoord, int qstride, const int* __restrict__ qidxmap,
                          const float* __restrict__ kcoord, int kstride, const int* __restrict__ kidxmap,
                          int Q, int Kn, int b, int qtile, int* __restrict__ nidx,
                          const int* __restrict__ omap,
                          bool dofeat, const float* __restrict__ Wt, const float* __restrict__ bt,
                          float* __restrict__ feat0)
{
    __shared__ float4 sk[BT];
    const int tid = threadIdx.x;
    int q = qtile*BT + tid;
    int qr = qidxmap ? qidxmap[b*Q + q] : q;
    float x = qcoord[(b*3+0)*qstride + qr];
    float y = qcoord[(b*3+1)*qstride + qr];
    float z = qcoord[(b*3+2)*qstride + qr];
    if (dofeat) {
        float f[8];
        #pragma unroll
        for (int o = 0; o < 8; o++)
            f[o] = fmaf(Wt[o*3+2], z, fmaf(Wt[o*3+1], y, fmaf(Wt[o*3+0], x, bt[o])));
        float4* dst = (float4*)&feat0[((size_t)(b*N0 + q))*8];
        dst[0] = make_float4(f[0], f[1], f[2], f[3]);
        dst[1] = make_float4(f[4], f[5], f[6], f[7]);
    }
    float q2 = __fadd_rn(__fadd_rn(__fmul_rn(x,x), __fmul_rn(y,y)), __fmul_rn(z,z));
    float bd[16]; int bi[16];
    #pragma unroll
    for (int r = 0; r < 16; r++) { bd[r] = 3.4e38f; bi[r] = 0; }
    for (int t0 = 0; t0 < Kn; t0 += BT) {
        int j  = t0 + tid;
        int kr = kidxmap ? kidxmap[b*Kn + j] : j;
        float kx = kcoord[(b*3+0)*kstride + kr];
        float ky = kcoord[(b*3+1)*kstride + kr];
        float kz = kcoord[(b*3+2)*kstride + kr];
        float k2 = __fadd_rn(__fadd_rn(__fmul_rn(kx,kx), __fmul_rn(ky,ky)), __fmul_rn(kz,kz));
        __syncthreads();
        sk[tid] = make_float4(kx, ky, kz, k2);
        __syncthreads();
        #pragma unroll 4
        for (int kk = 0; kk < BT; kk++) {
            float4 s  = sk[kk];
            float dot = __fadd_rn(__fadd_rn(__fmul_rn(x,s.x), __fmul_rn(y,s.y)), __fmul_rn(z,s.z));
            float d2  = __fsub_rn(__fadd_rn(q2, s.w), __fmul_rn(2.0f, dot));
            if (d2 < bd[15]) {
                bd[15] = d2; bi[15] = t0 + kk;
                #pragma unroll
                for (int r = 15; r > 0; --r) {
                    if (bd[r] < bd[r-1]) {
                        float td = bd[r]; bd[r] = bd[r-1]; bd[r-1] = td;
                        int   ti = bi[r]; bi[r] = bi[r-1]; bi[r-1] = ti;
                    }
                }
            }
        }
    }
    #pragma unroll
    for (int r = 0; r < 16; r++) {
        int v = bi[r];
        nidx[((size_t)(b*Q + q))*16 + r] = omap ? omap[b*Kn + v] : v;
    }
}

// ---------------- KNN split: 128 queries/block, 2 threads/query (key halves) --
__device__ void knn_split_block(const float* __restrict__ qc, const float* __restrict__ kc,
                                int b, int qtile, int* __restrict__ nidx)
{
    __shared__ float4 skk[512];
    __shared__ unsigned long long s_k[128][32];
    const int tid  = threadIdx.x;
    const int ql   = tid & 127;
    const int half = tid >> 7;
    int q = qtile*128 + ql;
    float x = qc[(b*3+0)*N1 + q];
    float y = qc[(b*3+1)*N1 + q];
    float z = qc[(b*3+2)*N1 + q];
    float q2 = __fadd_rn(__fadd_rn(__fmul_rn(x,x), __fmul_rn(y,y)), __fmul_rn(z,z));
    float bd[16]; int bi[16];
    #pragma unroll
    for (int r = 0; r < 16; r++) { bd[r] = 3.4e38f; bi[r] = 0; }
    const int kbase = half*2048;
    for (int t0 = 0; t0 < 2048; t0 += 256) {
        {
            int j0 = t0 + tid;
            float kx = kc[(b*3+0)*N0 + j0];
            float ky = kc[(b*3+1)*N0 + j0];
            float kz = kc[(b*3+2)*N0 + j0];
            float k2 = __fadd_rn(__fadd_rn(__fmul_rn(kx,kx), __fmul_rn(ky,ky)), __fmul_rn(kz,kz));
            int j1 = 2048 + t0 + tid;
            float kx1 = kc[(b*3+0)*N0 + j1];
            float ky1 = kc[(b*3+1)*N0 + j1];
            float kz1 = kc[(b*3+2)*N0 + j1];
            float k21 = __fadd_rn(__fadd_rn(__fmul_rn(kx1,kx1), __fmul_rn(ky1,ky1)), __fmul_rn(kz1,kz1));
            __syncthreads();
            skk[tid]       = make_float4(kx,  ky,  kz,  k2);
            skk[256 + tid] = make_float4(kx1, ky1, kz1, k21);
            __syncthreads();
        }
        const float4* sh = skk + half*256;
        #pragma unroll 4
        for (int kk = 0; kk < 256; kk++) {
            float4 s  = sh[kk];
            float dot = __fadd_rn(__fadd_rn(__fmul_rn(x,s.x), __fmul_rn(y,s.y)), __fmul_rn(z,s.z));
            float d2  = __fsub_rn(__fadd_rn(q2, s.w), __fmul_rn(2.0f, dot));
            if (d2 < bd[15]) {
                bd[15] = d2; bi[15] = kbase + t0 + kk;
                #pragma unroll
                for (int r = 15; r > 0; --r) {
                    if (bd[r] < bd[r-1]) {
                        float td = bd[r]; bd[r] = bd[r-1]; bd[r-1] = td;
                        int   ti = bi[r]; bi[r] = bi[r-1]; bi[r-1] = ti;
                    }
                }
            }
        }
    }
    #pragma unroll
    for (int r = 0; r < 16; r++) {
        unsigned dbits = __float_as_uint(bd[r]);
        dbits = (dbits & 0x80000000u) ? ~dbits : (dbits ^ 0x80000000u);   // total order
        s_k[ql][half*16 + r] = ((unsigned long long)dbits << 32) | (unsigned)bi[r];
    }
    __syncthreads();
    if (half == 0) {
        int ia = 0, ib = 0;
        #pragma unroll
        for (int r = 0; r < 16; r++) {
            unsigned long long ka = s_k[ql][min(ia,15)];
            unsigned long long kb = s_k[ql][16 + min(ib,15)];
            bool ta = (ib >= 16) || ((ia < 16) && (ka <= kb));  // tie -> half0 (lower idx)
            unsigned idx = (unsigned)(ta ? ka : kb);
            nidx[((size_t)(b*N1 + q))*16 + r] = (int)idx;
            ia += ta ? 1 : 0; ib += ta ? 0 : 1;
        }
    }
}

// ---------------- edge conv: shared-staged W, h in regs, hmax/hmin + stats ---
template<int CIN, int COUT, int QB>
__device__ void edge_block(float* sws, int eb,
                           const float* __restrict__ qf, int qrows, const int* __restrict__ qmap,
                           const float* __restrict__ kf, int Kn, const int* __restrict__ nidx,
                           const float* __restrict__ W,
                           float* __restrict__ hmax_o, float* __restrict__ hmin_o,
                           float* __restrict__ gsum, float* __restrict__ gsq, int Q)
{
    const int STR = 2*CIN + 4;
    const int NF4 = 2*CIN/4;
    float* s_W  = sws;
    float* s_nb = s_W + COUT*STR;
    float* s_qe = s_nb + QB*16*CIN;
    __shared__ float s_gs[4], s_gq[4];
    const int tid = threadIdx.x;
    const int b  = eb / (Q/QB);
    const int q0 = (eb % (Q/QB)) * QB;
    if (tid < 4) { s_gs[tid] = 0.f; s_gq[tid] = 0.f; }
    for (int i = tid; i < COUT*NF4; i += 256) {
        int o = i / NF4, j = i % NF4;
        *(float4*)&s_W[o*STR + j*4] = ((const float4*)W)[i];
    }
    for (int i = tid; i < QB*(CIN/4); i += 256) {
        int ql = i / (CIN/4), c4 = i % (CIN/4);
        int row = qmap ? qmap[b*Q + q0 + ql] : (q0 + ql);
        float4 v = *(const float4*)&qf[((size_t)b*qrows + row)*CIN + c4*4];
        *(float4*)&s_qe[ql*CIN + c4*4] = v;
    }
    for (int i = tid; i < QB*16*(CIN/4); i += 256) {
        int c4 = i % (CIN/4); int r = i / (CIN/4); int k = r & 15; int ql = r >> 4;
        int nb = nidx[((size_t)(b*Q + q0 + ql))*16 + k];
        float4 v = *(const float4*)&kf[((size_t)(b*Kn) + nb)*CIN + c4*4];
        *(float4*)&s_nb[(ql*16 + k)*CIN + c4*4] = v;
    }
    __syncthreads();
    const int ql = tid / COUT;
    const int o  = tid % COUT;
    float acc[16];
    #pragma unroll
    for (int k = 0; k < 16; k++) acc[k] = 0.f;
    float base = 0.f;
    const float* Wr  = s_W + o*STR;
    const float* qe_ = s_qe + ql*CIN;
    const float* nb_ = s_nb + ql*16*CIN;
    #pragma unroll
    for (int cc = 0; cc < CIN; cc += 4) {
        float4 w  = *(const float4*)&Wr[cc];
        float4 w2 = *(const float4*)&Wr[CIN + cc];
        float4 qe = *(const float4*)&qe_[cc];
        base = fmaf(w2.x - w.x, qe.x, base);
        base = fmaf(w2.y - w.y, qe.y, base);
        base = fmaf(w2.z - w.z, qe.z, base);
        base = fmaf(w2.w - w.w, qe.w, base);
        #pragma unroll
        for (int k = 0; k < 16; k++) {
            float4 nb4 = *(const float4*)&nb_[k*CIN + cc];
            acc[k] = fmaf(w.x, nb4.x, acc[k]);
            acc[k] = fmaf(w.y, nb4.y, acc[k]);
            acc[k] = fmaf(w.z, nb4.z, acc[k]);
            acc[k] = fmaf(w.w, nb4.w, acc[k]);
        }
    }
    float hmx = -3.4e38f, hmn = 3.4e38f, s = 0.f, sq = 0.f;
    #pragma unroll
    for (int k = 0; k < 16; k++) {
        float h = base + acc[k];
        hmx = fmaxf(hmx, h); hmn = fminf(hmn, h);
        s += h; sq = fmaf(h, h, sq);
    }
    const int width = (COUT/4 < 32) ? (COUT/4) : 32;
    #pragma unroll
    for (int off = width >> 1; off; off >>= 1) {
        s  += __shfl_down_sync(FULLMASK, s,  off, width);
        sq += __shfl_down_sync(FULLMASK, sq, off, width);
    }
    int g = o / (COUT/4);
    if ((o & (width-1)) == 0) { atomicAdd(&s_gs[g], s); atomicAdd(&s_gq[g], sq); }
    size_t ofs = ((size_t)(b*Q + q0 + ql))*COUT + o;
    hmax_o[ofs] = hmx; hmin_o[ofs] = hmn;
    __syncthreads();
    if (tid < 4) { atomicAdd(&gsum[b*4+tid], s_gs[tid]); atomicAdd(&gsq[b*4+tid], s_gq[tid]); }
}

// ---------------- finalize: y = leaky(hext*sc + sh) ---------------------------
__device__ void finalize_elem(int lin, const float* __restrict__ hmax, const float* __restrict__ hmin,
                              const float* __restrict__ gsum, const float* __restrict__ gsq,
                              const float* __restrict__ gamma, const float* __restrict__ beta,
                              float* __restrict__ out, int Q, int COUT, float inv_n, bool cf)
{
    int o = lin % COUT; int t = lin / COUT; int q = t % Q; int b = t / Q;
    int g = o / (COUT/4);
    float mean = gsum[b*4+g] * inv_n;
    float var  = gsq [b*4+g] * inv_n - mean*mean;
    float inv  = 1.0f / sqrtf(var + 1e-5f);
    float sc = gamma[o] * inv;
    float sh = beta[o] - mean * sc;
    float hv = (sc >= 0.f) ? hmax[lin] : hmin[lin];
    float yv = hv*sc + sh;
    yv = (yv >= 0.f) ? yv : 0.2f*yv;
    if (cf) out[(b*COUT + o)*Q + q] = yv;
    else    out[lin] = yv;
}

// ---------------- megakernels --------------------------------------------------
// blocks 0-3: dual fps (2 batches each, named-barrier groups); 4-67: knn1 (512t);
// 68: zero stats
__global__ void __launch_bounds__(512) kernelA(const float* __restrict__ pc,
                                               const float* __restrict__ Wt,
                                               const float* __restrict__ bt)
{
    __shared__ float s_sel[2][3*N1];
    __shared__ unsigned long long s_win[2][16];
    int blk = blockIdx.x;
    if (blk < 4) {
        int g = threadIdx.x >> 8;           // group 0/1
        int b = blk + 4*g;                  // batches 0-3 / 4-7
        fps_dual(pc, b, g, s_sel[g], s_win[g], d_fidx, d_fidx2);
    } else if (blk < 68) {
        int r = blk - 4;
        knn_block<512>(pc, N0, nullptr, pc, N0, nullptr, N0, N0, r/8, r%8,
                       d_nidx, nullptr, true, Wt, bt, d_feat0);
    } else {
        int t = threadIdx.x;
        if (t < 128) { d_gsum[t] = 0.f; d_gsq[t] = 0.f; }
    }
}

// edge1 || gather qc1
__global__ void __launch_bounds__(256) kernelB(const float* __restrict__ pc,
                                               const float* __restrict__ W1)
{
    __shared__ float ews[32*20 + 8*16*8 + 8*8];   // edge1 workspace (1728 floats)
    int blk = blockIdx.x;
    if (blk < 4096) {
        edge_block<8,32,8>(ews, blk, d_feat0, N0, nullptr, d_feat0, N0, d_nidx, W1,
                           d_hmax, d_hmin, d_gsum + 0, d_gsq + 0, N0);
    } else {
        int lin = (blk - 4096)*256 + threadIdx.x;      // B*3*N1 = 24576
        int j = lin % N1; int c = (lin/N1) % 3; int b = lin/(3*N1);
        d_qc1[lin] = pc[(b*3+c)*N0 + d_fidx[b*N1 + j]];
    }
}

// knn2(split) || knn3 || knn4 || finalize1
__global__ void __launch_bounds__(256) kernelC(const float* __restrict__ pc,
                                               const float* __restrict__ g1,
                                               const float* __restrict__ b1)
{
    int blk = blockIdx.x;
    if (blk < 64) {
        knn_split_block(d_qc1, pc, blk/8, blk%8, d_nidx);
    } else if (blk < 96) {
        int r = blk - 64;
        knn_block<256>(d_qc1, N1, nullptr, d_qc1, N1, nullptr, N1, N1, r/4, r%4,
                       d_nidx2, nullptr, false, nullptr, nullptr, nullptr);
    } else if (blk < 104) {
        knn_block<256>(d_qc1, N1, d_fidx2, d_qc1, N1, d_fidx2, N2, N2, blk - 96, 0,
                       d_nidx3, d_fidx2, false, nullptr, nullptr, nullptr);
    } else {
        int lin = (blk - 104)*256 + threadIdx.x;       // B*N0*32
        finalize_elem(lin, d_hmax, d_hmin, d_gsum + 0, d_gsq + 0, g1, b1,
                      d_kf1, N0, 32, 1.0f/(8.0f*N0*16.0f), false);
    }
}

__global__ void __launch_bounds__(256) kernelD(const float* __restrict__ W2)
{
    extern __shared__ float dsm[];
    edge_block<32,64,4>(dsm, blockIdx.x, d_kf1, N0, d_fidx, d_kf1, N0, d_nidx, W2,
                        d_hmax, d_hmin, d_gsum + 32, d_gsq + 32, N1);
}

__global__ void __launch_bounds__(256) kernelE(const float* __restrict__ g2,
                                               const float* __restrict__ b2)
{
    int lin = blockIdx.x*256 + threadIdx.x;            // B*N1*64
    finalize_elem(lin, d_hmax, d_hmin, d_gsum + 32, d_gsq + 32, g2, b2,
                  d_qf2, N1, 64, 1.0f/(16.0f*N1*16.0f), false);
}

__global__ void __launch_bounds__(256) kernelF(const float* __restrict__ W3)
{
    extern __shared__ float dsm[];
    edge_block<64,64,4>(dsm, blockIdx.x, d_qf2, N1, nullptr, d_qf2, N1, d_nidx2, W3,
                        d_hmax, d_hmin, d_gsum + 64, d_gsq + 64, N1);
}

__global__ void __launch_bounds__(256) kernelG(const float* __restrict__ g3,
                                               const float* __restrict__ b3,
                                               float* __restrict__ qc_out)
{
    int blk = blockIdx.x;
    if (blk < 2048) {
        int lin = blk*256 + threadIdx.x;               // B*N1*64
        finalize_elem(lin, d_hmax, d_hmin, d_gsum + 64, d_gsq + 64, g3, b3,
                      d_kf3, N1, 64, 1.0f/(16.0f*N1*16.0f), false);
    } else {
        int lin = (blk - 2048)*256 + threadIdx.x;      // B*3*N2 = 6144
        int j = lin % N2; int c = (lin/N2) % 3; int b = lin/(3*N2);
        qc_out[lin] = d_qc1[(b*3+c)*N1 + d_fidx2[b*N2 + j]];
    }
}

__global__ void __launch_bounds__(256) kernelH(const float* __restrict__ W4)
{
    extern __shared__ float dsm[];
    edge_block<64,128,2>(dsm, blockIdx.x, d_kf3, N1, d_fidx2, d_kf3, N1, d_nidx3, W4,
                         d_hmax, d_hmin, d_gsum + 96, d_gsq + 96, N2);
}

__global__ void __launch_bounds__(256) kernelI(const float* __restrict__ g4,
                                               const float* __restrict__ b4,
                                               float* __restrict__ qf_out)
{
    int lin = blockIdx.x*256 + threadIdx.x;            // B*N2*128
    finalize_elem(lin, d_hmax, d_hmin, d_gsum + 96, d_gsq + 96, g4, b4,
                  qf_out, N2, 128, 1.0f/(32.0f*N2*16.0f), true);
}

// ---------------- launch --------------------------------------------------------
extern "C" void kernel_launch(void* const* d_in, const int* in_sizes, int n_in,
                              void* d_out, int out_size) {
    const float* pc = (const float*)d_in[0];
    const float* Wt = (const float*)d_in[1];
    const float* bt = (const float*)d_in[2];
    const float* W1 = (const float*)d_in[3];
    const float* g1 = (const float*)d_in[4];
    const float* b1 = (const float*)d_in[5];
    const float* W2 = (const float*)d_in[6];
    const float* g2 = (const float*)d_in[7];
    const float* b2 = (const float*)d_in[8];
    const float* W3 = (const float*)d_in[9];
    const float* g3 = (const float*)d_in[10];
    const float* b3 = (const float*)d_in[11];
    const float* W4 = (const float*)d_in[12];
    const float* g4 = (const float*)d_in[13];
    const float* b4 = (const float*)d_in[14];

    float* out    = (float*)d_out;
    float* qc_out = out;                  // (B,3,256)
    float* qf_out = out + B*3*N2;         // (B,128,256)

    const int smemD = (64*68  + 4*16*32 + 4*32) * 4;   // 26112 B
    const int smemF = (64*132 + 4*16*64 + 4*64) * 4;   // 51200 B
    const int smemH = (128*132 + 2*16*64 + 2*64) * 4;  // 76288 B
    cudaFuncSetAttribute(kernelF, cudaFuncAttributeMaxDynamicSharedMemorySize, smemF);
    cudaFuncSetAttribute(kernelH, cudaFuncAttributeMaxDynamicSharedMemorySize, smemH);

    kernelA<<<69, 512>>>(pc, Wt, bt);                  // fps1+fps2 (dual) || knn1+feat || zero
    kernelB<<<4192, 256>>>(pc, W1);                    // edge1 || gather qc1
    kernelC<<<4200, 256>>>(pc, g1, b1);                // knn2split||knn3||knn4||finalize1
    kernelD<<<2048, 256, smemD>>>(W2);                 // edge2
    kernelE<<<2048, 256>>>(g2, b2);                    // finalize2 -> qf2
    kernelF<<<2048, 256, smemF>>>(W3);                 // edge3
    kernelG<<<2072, 256>>>(g3, b3, qc_out);            // finalize3 -> kf3 || qc_out
    kernelH<<<1024, 256, smemH>>>(W4);                 // edge4
    kernelI<<<1024, 256>>>(g4, b4, qf_out);            // finalize4 -> qf_out
}

// round 15
// speedup vs baseline: 1.0047x; 1.0010x over previous
#include <cuda_runtime.h>
#include <math.h>
#include <stdint.h>

#define FULLMASK 0xffffffffu

static const int B  = 8;
static const int N0 = 4096;
static const int N1 = 1024;
static const int N2 = 256;

// ---------------- scratch (device globals) ----------------------------------
__device__ float d_feat0[B*N0*8];      // (B,N0,8)  channels-last
__device__ float d_kf1  [B*N0*32];     // (B,N0,32) channels-last
__device__ float d_qc1  [B*3*N1];      // (B,3,N1)  channels-first
__device__ float d_qf2  [B*N1*64];     // (B,N1,64)
__device__ float d_kf3  [B*N1*64];     // (B,N1,64)
__device__ float d_hmax [B*N0*32];     // per-(b,q,o) max_k h (reused per layer)
__device__ float d_hmin [B*N0*32];
__device__ int   d_nidx [B*N0*16];     // knn layer1/2 indices
__device__ int   d_nidx2[B*N1*16];     // knn layer3
__device__ int   d_nidx3[B*N2*16];     // knn layer4
__device__ int   d_fidx [B*N1];        // fps1 indices
__device__ int   d_fidx2[B*N2];        // fps2 indices (local into N1 subset)
__device__ float d_gsum [4*B*4];
__device__ float d_gsq  [4*B*4];

// ---------------- warp redux / barrier helpers --------------------------------
__device__ __forceinline__ unsigned redux_max_u32(unsigned v) {
    unsigned r; asm("redux.sync.max.u32 %0, %1, 0xffffffff;" : "=r"(r) : "r"(v)); return r;
}
__device__ __forceinline__ unsigned redux_min_u32(unsigned v) {
    unsigned r; asm("redux.sync.min.u32 %0, %1, 0xffffffff;" : "=r"(r) : "r"(v)); return r;
}
__device__ __forceinline__ void bar_named(int id) {
    asm volatile("bar.sync %0, 256;" :: "r"(id) : "memory");
}

// ---------------- packed f32x2 helpers ----------------------------------------
__device__ __forceinline__ unsigned long long pack2(float lo, float hi) {
    unsigned long long v;
    asm("mov.b64 %0, {%1, %2};" : "=l"(v) : "f"(lo), "f"(hi));
    return v;
}
// d = ((x-lx)^2 + (y-ly)^2) + (z-lz)^2 for two points, per-lane rn arithmetic
// (add of negated value == sub, mul/add rounding identical to scalar path).
__device__ __forceinline__ void dist2_pair(
    unsigned long long px2, unsigned long long py2, unsigned long long pz2,
    unsigned long long nlx2, unsigned long long nly2, unsigned long long nlz2,
    float& d0, float& d1)
{
    unsigned long long dx, dy, dz, s;
    asm("add.rn.f32x2 %0, %1, %2;" : "=l"(dx) : "l"(px2), "l"(nlx2));
    asm("add.rn.f32x2 %0, %1, %2;" : "=l"(dy) : "l"(py2), "l"(nly2));
    asm("add.rn.f32x2 %0, %1, %2;" : "=l"(dz) : "l"(pz2), "l"(nlz2));
    asm("mul.rn.f32x2 %0, %1, %1;" : "=l"(dx) : "l"(dx));
    asm("mul.rn.f32x2 %0, %1, %1;" : "=l"(dy) : "l"(dy));
    asm("mul.rn.f32x2 %0, %1, %1;" : "=l"(dz) : "l"(dz));
    asm("add.rn.f32x2 %0, %1, %2;" : "=l"(s)  : "l"(dx), "l"(dy));
    asm("add.rn.f32x2 %0, %1, %2;" : "=l"(s)  : "l"(s),  "l"(dz));
    asm("mov.b64 {%0, %1}, %2;" : "=f"(d0), "=f"(d1) : "l"(s));
}

// thread-local argmax over dd[NPT]: max via FMNMX tree, then min encoded index
// among exact-equal values (matches scan-order tie-break).
template<int NPT>
__device__ __forceinline__ void fps_argmax(const float* dd, int t, float& bv, int& bi)
{
    float m[NPT];
    #pragma unroll
    for (int p = 0; p < NPT; p++) m[p] = dd[p];
    #pragma unroll
    for (int s = NPT/2; s > 0; s >>= 1)
        #pragma unroll
        for (int p = 0; p < s; p++) m[p] = fmaxf(m[p], m[p+s]);
    bv = m[0];
    int enc[NPT];
    #pragma unroll
    for (int p = 0; p < NPT; p++)
        enc[p] = (dd[p] == bv) ? (t + (p << 8)) : 0x7FFFFFFF;
    #pragma unroll
    for (int s = NPT/2; s > 0; s >>= 1)
        #pragma unroll
        for (int p = 0; p < s; p++) enc[p] = min(enc[p], enc[p+s]);
    bi = enc[0];
}

// post-barrier 8-slot winner: pairwise u64 tree (depth 3)
__device__ __forceinline__ int fps_block_winner(const unsigned long long* slot)
{
    unsigned long long v0 = slot[0], v1 = slot[1], v2 = slot[2], v3 = slot[3];
    unsigned long long v4 = slot[4], v5 = slot[5], v6 = slot[6], v7 = slot[7];
    unsigned long long a = (v0 > v1) ? v0 : v1;
    unsigned long long b = (v2 > v3) ? v2 : v3;
    unsigned long long c = (v4 > v5) ? v4 : v5;
    unsigned long long d = (v6 > v7) ? v6 : v7;
    a = (a > b) ? a : b;
    c = (c > d) ? c : d;
    a = (a > c) ? a : c;
    return (int)(~(unsigned)a);
}

// ---------------- dual-FPS: one 256-thread group does fps1 then fps2 ----------
// Group g of the block handles batch b. Named barrier (1+g) syncs the group.
// Selected coords stashed in s_sel (3*N1 floats) during fps1; fps2 runs on them.
__device__ void fps_dual(const float* __restrict__ pc, int b, int g,
                         float* s_sel, unsigned long long* s_win,
                         int* __restrict__ outidx1, int* __restrict__ outidx2)
{
    const int t = threadIdx.x & 255;
    const int barid = 1 + g;
    float* s_sx = s_sel;
    float* s_sy = s_sel + N1;
    float* s_sz = s_sel + 2*N1;
    const float* cx = pc + (b*3+0)*N0;
    const float* cy = pc + (b*3+1)*N0;
    const float* cz = pc + (b*3+2)*N0;

    // ---- fps1: 4096 -> 1024, 16 pts/thread ----
    {
        unsigned long long px2[8], py2[8], pz2[8];
        float dd[16];
        #pragma unroll
        for (int p = 0; p < 8; p++) {
            int i0 = t + ((2*p)   << 8);
            int i1 = t + ((2*p+1) << 8);
            px2[p] = pack2(cx[i0], cx[i1]);
            py2[p] = pack2(cy[i0], cy[i1]);
            pz2[p] = pack2(cz[i0], cz[i1]);
            dd[2*p] = 1e10f; dd[2*p+1] = 1e10f;
        }
        float lx = cx[0], ly = cy[0], lz = cz[0];
        if (t == 0) {
            outidx1[b*N1] = 0;
            s_sx[0] = lx; s_sy[0] = ly; s_sz[0] = lz;
        }
        for (int it = 1; it < N1; ++it) {
            unsigned long long nlx2 = pack2(-lx, -lx);
            unsigned long long nly2 = pack2(-ly, -ly);
            unsigned long long nlz2 = pack2(-lz, -lz);
            #pragma unroll
            for (int p = 0; p < 8; p++) {
                float d0, d1;
                dist2_pair(px2[p], py2[p], pz2[p], nlx2, nly2, nlz2, d0, d1);
                dd[2*p]   = fminf(dd[2*p],   d0);
                dd[2*p+1] = fminf(dd[2*p+1], d1);
            }
            float bv; int bi;
            fps_argmax<16>(dd, t, bv, bi);
            unsigned db = __float_as_uint(bv);
            unsigned m  = redux_max_u32(db);
            unsigned mi = redux_min_u32(db == m ? (unsigned)bi : 0xFFFFFFFFu);
            int cur = it & 1;
            if ((t & 31) == 0)
                s_win[cur*8 + (t >> 5)] = ((unsigned long long)m << 32) | (unsigned)(~mi);
            bar_named(barid);
            int sel = fps_block_winner(&s_win[cur*8]);
            if (t == 0) outidx1[b*N1 + it] = sel;
            lx = cx[sel]; ly = cy[sel]; lz = cz[sel];
            if (t == 0) { s_sx[it] = lx; s_sy[it] = ly; s_sz[it] = lz; }
        }
    }
    bar_named(barid);   // make s_sel visible to the group

    // ---- fps2: 1024 -> 256 on stashed coords, 4 pts/thread ----
    {
        unsigned long long px2[2], py2[2], pz2[2];
        float dd[4];
        #pragma unroll
        for (int p = 0; p < 2; p++) {
            int i0 = t + ((2*p)   << 8);
            int i1 = t + ((2*p+1) << 8);
            px2[p] = pack2(s_sx[i0], s_sx[i1]);
            py2[p] = pack2(s_sy[i0], s_sy[i1]);
            pz2[p] = pack2(s_sz[i0], s_sz[i1]);
            dd[2*p] = 1e10f; dd[2*p+1] = 1e10f;
        }
        float lx = s_sx[0], ly = s_sy[0], lz = s_sz[0];
        if (t == 0) outidx2[b*N2] = 0;
        for (int it = 1; it < N2; ++it) {
            unsigned long long nlx2 = pack2(-lx, -lx);
            unsigned long long nly2 = pack2(-ly, -ly);
            unsigned long long nlz2 = pack2(-lz, -lz);
            #pragma unroll
            for (int p = 0; p < 2; p++) {
                float d0, d1;
                dist2_pair(px2[p], py2[p], pz2[p], nlx2, nly2, nlz2, d0, d1);
                dd[2*p]   = fminf(dd[2*p],   d0);
                dd[2*p+1] = fminf(dd[2*p+1], d1);
            }
            float bv; int bi;
            fps_argmax<4>(dd, t, bv, bi);
            unsigned db = __float_as_uint(bv);
            unsigned m  = redux_max_u32(db);
            unsigned mi = redux_min_u32(db == m ? (unsigned)bi : 0xFFFFFFFFu);
            int cur = it & 1;
            if ((t & 31) == 0)
                s_win[cur*8 + (t >> 5)] = ((unsigned long long)m << 32) | (unsigned)(~mi);
            bar_named(barid);
            int sel = fps_block_winner(&s_win[cur*8]);
            if (t == 0) outidx2[b*N2 + it] = sel;
            lx = s_sx[sel]; ly = s_sy[sel]; lz = s_sz[sel];
        }
    }
}

// ---------------- KNN: BT queries/block, optional indirection + feat ---------
template<int BT>
__device__ void knn_block(const float* __restrict__ qcoord, int qstride, const int* __restrict__ qidxmap,
                          const float* __restrict__ kcoord, int kstride, const int* __restrict__ kidxmap,
                          int Q, int Kn, int b, int qtile, int* __restrict__ nidx,
                          const int* __restrict__ omap,
                          bool dofeat, const float* __restrict__ Wt, const float* __restrict__ bt,
                          float* __restrict__ feat0)
{
    __shared__ float4 sk[BT];
    const int tid = threadIdx.x;
    int q = qtile*BT + tid;
    int qr = qidxmap ? qidxmap[b*Q + q] : q;
    float x = qcoord[(b*3+0)*qstride + qr];
    float y = qcoord[(b*3+1)*qstride + qr];
    float z = qcoord[(b*3+2)*qstride + qr];
    if (dofeat) {
        float f[8];
        #pragma unroll
        for (int o = 0; o < 8; o++)
            f[o] = fmaf(Wt[o*3+2], z, fmaf(Wt[o*3+1], y, fmaf(Wt[o*3+0], x, bt[o])));
        float4* dst = (float4*)&feat0[((size_t)(b*N0 + q))*8];
        dst[0] = make_float4(f[0], f[1], f[2], f[3]);
        dst[1] = make_float4(f[4], f[5], f[6], f[7]);
    }
    float q2 = __fadd_rn(__fadd_rn(__fmul_rn(x,x), __fmul_rn(y,y)), __fmul_rn(z,z));
    float bd[16]; int bi[16];
    #pragma unroll
    for (int r = 0; r < 16; r++) { bd[r] = 3.4e38f; bi[r] = 0; }
    for (int t0 = 0; t0 < Kn; t0 += BT) {
        int j  = t0 + tid;
        int kr = kidxmap ? kidxmap[b*Kn + j] : j;
        float kx = kcoord[(b*3+0)*kstride + kr];
        float ky = kcoord[(b*3+1)*kstride + kr];
        float kz = kcoord[(b*3+2)*kstride + kr];
        float k2 = __fadd_rn(__fadd_rn(__fmul_rn(kx,kx), __fmul_rn(ky,ky)), __fmul_rn(kz,kz));
        __syncthreads();
        sk[tid] = make_float4(kx, ky, kz, k2);
        __syncthreads();
        #pragma unroll 4
        for (int kk = 0; kk < BT; kk++) {
            float4 s  = sk[kk];
            float dot = __fadd_rn(__fadd_rn(__fmul_rn(x,s.x), __fmul_rn(y,s.y)), __fmul_rn(z,s.z));
            float d2  = __fsub_rn(__fadd_rn(q2, s.w), __fmul_rn(2.0f, dot));
            if (d2 < bd[15]) {
                bd[15] = d2; bi[15] = t0 + kk;
                #pragma unroll
                for (int r = 15; r > 0; --r) {
                    if (bd[r] < bd[r-1]) {
                        float td = bd[r]; bd[r] = bd[r-1]; bd[r-1] = td;
                        int   ti = bi[r]; bi[r] = bi[r-1]; bi[r-1] = ti;
                    }
                }
            }
        }
    }
    #pragma unroll
    for (int r = 0; r < 16; r++) {
        int v = bi[r];
        nidx[((size_t)(b*Q + q))*16 + r] = omap ? omap[b*Kn + v] : v;
    }
}

// ---------------- KNN split: 128 queries/block, 2 threads/query (key halves) --
__device__ void knn_split_block(const float* __restrict__ qc, const float* __restrict__ kc,
                                int b, int qtile, int* __restrict__ nidx)
{
    __shared__ float4 skk[512];
    __shared__ unsigned long long s_k[128][32];
    const int tid  = threadIdx.x;
    const int ql   = tid & 127;
    const int half = tid >> 7;
    int q = qtile*128 + ql;
    float x = qc[(b*3+0)*N1 + q];
    float y = qc[(b*3+1)*N1 + q];
    float z = qc[(b*3+2)*N1 + q];
    float q2 = __fadd_rn(__fadd_rn(__fmul_rn(x,x), __fmul_rn(y,y)), __fmul_rn(z,z));
    float bd[16]; int bi[16];
    #pragma unroll
    for (int r = 0; r < 16; r++) { bd[r] = 3.4e38f; bi[r] = 0; }
    const int kbase = half*2048;
    for (int t0 = 0; t0 < 2048; t0 += 256) {
        {
            int j0 = t0 + tid;
            float kx = kc[(b*3+0)*N0 + j0];
            float ky = kc[(b*3+1)*N0 + j0];
            float kz = kc[(b*3+2)*N0 + j0];
            float k2 = __fadd_rn(__fadd_rn(__fmul_rn(kx,kx), __fmul_rn(ky,ky)), __fmul_rn(kz,kz));
            int j1 = 2048 + t0 + tid;
            float kx1 = kc[(b*3+0)*N0 + j1];
            float ky1 = kc[(b*3+1)*N0 + j1];
            float kz1 = kc[(b*3+2)*N0 + j1];
            float k21 = __fadd_rn(__fadd_rn(__fmul_rn(kx1,kx1), __fmul_rn(ky1,ky1)), __fmul_rn(kz1,kz1));
            __syncthreads();
            skk[tid]       = make_float4(kx,  ky,  kz,  k2);
            skk[256 + tid] = make_float4(kx1, ky1, kz1, k21);
            __syncthreads();
        }
        const float4* sh = skk + half*256;
        #pragma unroll 4
        for (int kk = 0; kk < 256; kk++) {
            float4 s  = sh[kk];
            float dot = __fadd_rn(__fadd_rn(__fmul_rn(x,s.x), __fmul_rn(y,s.y)), __fmul_rn(z,s.z));
            float d2  = __fsub_rn(__fadd_rn(q2, s.w), __fmul_rn(2.0f, dot));
            if (d2 < bd[15]) {
                bd[15] = d2; bi[15] = kbase + t0 + kk;
                #pragma unroll
                for (int r = 15; r > 0; --r) {
                    if (bd[r] < bd[r-1]) {
                        float td = bd[r]; bd[r] = bd[r-1]; bd[r-1] = td;
                        int   ti = bi[r]; bi[r] = bi[r-1]; bi[r-1] = ti;
                    }
                }
            }
        }
    }
    #pragma unroll
    for (int r = 0; r < 16; r++) {
        unsigned dbits = __float_as_uint(bd[r]);
        dbits = (dbits & 0x80000000u) ? ~dbits : (dbits ^ 0x80000000u);   // total order
        s_k[ql][half*16 + r] = ((unsigned long long)dbits << 32) | (unsigned)bi[r];
    }
    __syncthreads();
    if (half == 0) {
        int ia = 0, ib = 0;
        #pragma unroll
        for (int r = 0; r < 16; r++) {
            unsigned long long ka = s_k[ql][min(ia,15)];
            unsigned long long kb = s_k[ql][16 + min(ib,15)];
            bool ta = (ib >= 16) || ((ia < 16) && (ka <= kb));  // tie -> half0 (lower idx)
            unsigned idx = (unsigned)(ta ? ka : kb);
            nidx[((size_t)(b*N1 + q))*16 + r] = (int)idx;
            ia += ta ? 1 : 0; ib += ta ? 0 : 1;
        }
    }
}

// ---------------- edge conv: shared-staged W, h in regs, hmax/hmin + stats ---
template<int CIN, int COUT, int QB>
__device__ void edge_block(float* sws, int eb,
                           const float* __restrict__ qf, int qrows, const int* __restrict__ qmap,
                           const float* __restrict__ kf, int Kn, const int* __restrict__ nidx,
                           const float* __restrict__ W,
                           float* __restrict__ hmax_o, float* __restrict__ hmin_o,
                           float* __restrict__ gsum, float* __restrict__ gsq, int Q)
{
    const int STR = 2*CIN + 4;
    const int NF4 = 2*CIN/4;
    float* s_W  = sws;
    float* s_nb = s_W + COUT*STR;
    float* s_qe = s_nb + QB*16*CIN;
    __shared__ float s_gs[4], s_gq[4];
    const int tid = threadIdx.x;
    const int b  = eb / (Q/QB);
    const int q0 = (eb % (Q/QB)) * QB;
    if (tid < 4) { s_gs[tid] = 0.f; s_gq[tid] = 0.f; }
    for (int i = tid; i < COUT*NF4; i += 256) {
        int o = i / NF4, j = i % NF4;
        *(float4*)&s_W[o*STR + j*4] = ((const float4*)W)[i];
    }
    for (int i = tid; i < QB*(CIN/4); i += 256) {
        int ql = i / (CIN/4), c4 = i % (CIN/4);
        int row = qmap ? qmap[b*Q + q0 + ql] : (q0 + ql);
        float4 v = *(const float4*)&qf[((size_t)b*qrows + row)*CIN + c4*4];
        *(float4*)&s_qe[ql*CIN + c4*4] = v;
    }
    for (int i = tid; i < QB*16*(CIN/4); i += 256) {
        int c4 = i % (CIN/4); int r = i / (CIN/4); int k = r & 15; int ql = r >> 4;
        int nb = nidx[((size_t)(b*Q + q0 + ql))*16 + k];
        float4 v = *(const float4*)&kf[((size_t)(b*Kn) + nb)*CIN + c4*4];
        *(float4*)&s_nb[(ql*16 + k)*CIN + c4*4] = v;
    }
    __syncthreads();
    const int ql = tid / COUT;
    const int o  = tid % COUT;
    float acc[16];
    #pragma unroll
    for (int k = 0; k < 16; k++) acc[k] = 0.f;
    float base = 0.f;
    const float* Wr  = s_W + o*STR;
    const float* qe_ = s_qe + ql*CIN;
    const float* nb_ = s_nb + ql*16*CIN;
    #pragma unroll
    for (int cc = 0; cc < CIN; cc += 4) {
        float4 w  = *(const float4*)&Wr[cc];
        float4 w2 = *(const float4*)&Wr[CIN + cc];
        float4 qe = *(const float4*)&qe_[cc];
        base = fmaf(w2.x - w.x, qe.x, base);
        base = fmaf(w2.y - w.y, qe.y, base);
        base = fmaf(w2.z - w.z, qe.z, base);
        base = fmaf(w2.w - w.w, qe.w, base);
        #pragma unroll
        for (int k = 0; k < 16; k++) {
            float4 nb4 = *(const float4*)&nb_[k*CIN + cc];
            acc[k] = fmaf(w.x, nb4.x, acc[k]);
            acc[k] = fmaf(w.y, nb4.y, acc[k]);
            acc[k] = fmaf(w.z, nb4.z, acc[k]);
            acc[k] = fmaf(w.w, nb4.w, acc[k]);
        }
    }
    float hmx = -3.4e38f, hmn = 3.4e38f, s = 0.f, sq = 0.f;
    #pragma unroll
    for (int k = 0; k < 16; k++) {
        float h = base + acc[k];
        hmx = fmaxf(hmx, h); hmn = fminf(hmn, h);
        s += h; sq = fmaf(h, h, sq);
    }
    const int width = (COUT/4 < 32) ? (COUT/4) : 32;
    #pragma unroll
    for (int off = width >> 1; off; off >>= 1) {
        s  += __shfl_down_sync(FULLMASK, s,  off, width);
        sq += __shfl_down_sync(FULLMASK, sq, off, width);
    }
    int g = o / (COUT/4);
    if ((o & (width-1)) == 0) { atomicAdd(&s_gs[g], s); atomicAdd(&s_gq[g], sq); }
    size_t ofs = ((size_t)(b*Q + q0 + ql))*COUT + o;
    hmax_o[ofs] = hmx; hmin_o[ofs] = hmn;
    __syncthreads();
    if (tid < 4) { atomicAdd(&gsum[b*4+tid], s_gs[tid]); atomicAdd(&gsq[b*4+tid], s_gq[tid]); }
}

// ---------------- finalize: y = leaky(hext*sc + sh) ---------------------------
__device__ void finalize_elem(int lin, const float* __restrict__ hmax, const float* __restrict__ hmin,
                              const float* __restrict__ gsum, const float* __restrict__ gsq,
                              const float* __restrict__ gamma, const float* __restrict__ beta,
                              float* __restrict__ out, int Q, int COUT, float inv_n, bool cf)
{
    int o = lin % COUT; int t = lin / COUT; int q = t % Q; int b = t / Q;
    int g = o / (COUT/4);
    float mean = gsum[b*4+g] * inv_n;
    float var  = gsq [b*4+g] * inv_n - mean*mean;
    float inv  = 1.0f / sqrtf(var + 1e-5f);
    float sc = gamma[o] * inv;
    float sh = beta[o] - mean * sc;
    float hv = (sc >= 0.f) ? hmax[lin] : hmin[lin];
    float yv = hv*sc + sh;
    yv = (yv >= 0.f) ? yv : 0.2f*yv;
    if (cf) out[(b*COUT + o)*Q + q] = yv;
    else    out[lin] = yv;
}

// ---------------- megakernels --------------------------------------------------
// blocks 0-3: dual fps (2 batches each, named-barrier groups); 4-67: knn1 (512t);
// 68: zero stats
__global__ void __launch_bounds__(512) kernelA(const float* __restrict__ pc,
                                               const float* __restrict__ Wt,
                                               const float* __restrict__ bt)
{
    __shared__ float s_sel[2][3*N1];
    __shared__ unsigned long long s_win[2][16];
    int blk = blockIdx.x;
    if (blk < 4) {
        int g = threadIdx.x >> 8;           // group 0/1
        int b = blk + 4*g;                  // batches 0-3 / 4-7
        fps_dual(pc, b, g, s_sel[g], s_win[g], d_fidx, d_fidx2);
    } else if (blk < 68) {
        int r = blk - 4;
        knn_block<512>(pc, N0, nullptr, pc, N0, nullptr, N0, N0, r/8, r%8,
                       d_nidx, nullptr, true, Wt, bt, d_feat0);
    } else {
        int t = threadIdx.x;
        if (t < 128) { d_gsum[t] = 0.f; d_gsq[t] = 0.f; }
    }
}

// edge1 || gather qc1
__global__ void __launch_bounds__(256) kernelB(const float* __restrict__ pc,
                                               const float* __restrict__ W1)
{
    __shared__ float ews[32*20 + 8*16*8 + 8*8];   // edge1 workspace (1728 floats)
    int blk = blockIdx.x;
    if (blk < 4096) {
        edge_block<8,32,8>(ews, blk, d_feat0, N0, nullptr, d_feat0, N0, d_nidx, W1,
                           d_hmax, d_hmin, d_gsum + 0, d_gsq + 0, N0);
    } else {
        int lin = (blk - 4096)*256 + threadIdx.x;      // B*3*N1 = 24576
        int j = lin % N1; int c = (lin/N1) % 3; int b = lin/(3*N1);
        d_qc1[lin] = pc[(b*3+c)*N0 + d_fidx[b*N1 + j]];
    }
}

// knn2(split) || knn3 || knn4 || finalize1
__global__ void __launch_bounds__(256) kernelC(const float* __restrict__ pc,
                                               const float* __restrict__ g1,
                                               const float* __restrict__ b1)
{
    int blk = blockIdx.x;
    if (blk < 64) {
        knn_split_block(d_qc1, pc, blk/8, blk%8, d_nidx);
    } else if (blk < 96) {
        int r = blk - 64;
        knn_block<256>(d_qc1, N1, nullptr, d_qc1, N1, nullptr, N1, N1, r/4, r%4,
                       d_nidx2, nullptr, false, nullptr, nullptr, nullptr);
    } else if (blk < 104) {
        knn_block<256>(d_qc1, N1, d_fidx2, d_qc1, N1, d_fidx2, N2, N2, blk - 96, 0,
                       d_nidx3, d_fidx2, false, nullptr, nullptr, nullptr);
    } else {
        int lin = (blk - 104)*256 + threadIdx.x;       // B*N0*32
        finalize_elem(lin, d_hmax, d_hmin, d_gsum + 0, d_gsq + 0, g1, b1,
                      d_kf1, N0, 32, 1.0f/(8.0f*N0*16.0f), false);
    }
}

__global__ void __launch_bounds__(256) kernelD(const float* __restrict__ W2)
{
    extern __shared__ float dsm[];
    edge_block<32,64,4>(dsm, blockIdx.x, d_kf1, N0, d_fidx, d_kf1, N0, d_nidx, W2,
                        d_hmax, d_hmin, d_gsum + 32, d_gsq + 32, N1);
}

__global__ void __launch_bounds__(256) kernelE(const float* __restrict__ g2,
                                               const float* __restrict__ b2)
{
    int lin = blockIdx.x*256 + threadIdx.x;            // B*N1*64
    finalize_elem(lin, d_hmax, d_hmin, d_gsum + 32, d_gsq + 32, g2, b2,
                  d_qf2, N1, 64, 1.0f/(16.0f*N1*16.0f), false);
}

__global__ void __launch_bounds__(256) kernelF(const float* __restrict__ W3)
{
    extern __shared__ float dsm[];
    edge_block<64,64,4>(dsm, blockIdx.x, d_qf2, N1, nullptr, d_qf2, N1, d_nidx2, W3,
                        d_hmax, d_hmin, d_gsum + 64, d_gsq + 64, N1);
}

__global__ void __launch_bounds__(256) kernelG(const float* __restrict__ g3,
                                               const float* __restrict__ b3,
                                               float* __restrict__ qc_out)
{
    int blk = blockIdx.x;
    if (blk < 2048) {
        int lin = blk*256 + threadIdx.x;               // B*N1*64
        finalize_elem(lin, d_hmax, d_hmin, d_gsum + 64, d_gsq + 64, g3, b3,
                      d_kf3, N1, 64, 1.0f/(16.0f*N1*16.0f), false);
    } else {
        int lin = (blk - 2048)*256 + threadIdx.x;      // B*3*N2 = 6144
        int j = lin % N2; int c = (lin/N2) % 3; int b = lin/(3*N2);
        qc_out[lin] = d_qc1[(b*3+c)*N1 + d_fidx2[b*N2 + j]];
    }
}

__global__ void __launch_bounds__(256) kernelH(const float* __restrict__ W4)
{
    extern __shared__ float dsm[];
    edge_block<64,128,2>(dsm, blockIdx.x, d_kf3, N1, d_fidx2, d_kf3, N1, d_nidx3, W4,
                         d_hmax, d_hmin, d_gsum + 96, d_gsq + 96, N2);
}

__global__ void __launch_bounds__(256) kernelI(const float* __restrict__ g4,
                                               const float* __restrict__ b4,
                                               float* __restrict__ qf_out)
{
    int lin = blockIdx.x*256 + threadIdx.x;            // B*N2*128
    finalize_elem(lin, d_hmax, d_hmin, d_gsum + 96, d_gsq + 96, g4, b4,
                  qf_out, N2, 128, 1.0f/(32.0f*N2*16.0f), true);
}

// ---------------- launch --------------------------------------------------------
extern "C" void kernel_launch(void* const* d_in, const int* in_sizes, int n_in,
                              void* d_out, int out_size) {
    const float* pc = (const float*)d_in[0];
    const float* Wt = (const float*)d_in[1];
    const float* bt = (const float*)d_in[2];
    const float* W1 = (const float*)d_in[3];
    const float* g1 = (const float*)d_in[4];
    const float* b1 = (const float*)d_in[5];
    const float* W2 = (const float*)d_in[6];
    const float* g2 = (const float*)d_in[7];
    const float* b2 = (const float*)d_in[8];
    const float* W3 = (const float*)d_in[9];
    const float* g3 = (const float*)d_in[10];
    const float* b3 = (const float*)d_in[11];
    const float* W4 = (const float*)d_in[12];
    const float* g4 = (const float*)d_in[13];
    const float* b4 = (const float*)d_in[14];

    float* out    = (float*)d_out;
    float* qc_out = out;                  // (B,3,256)
    float* qf_out = out + B*3*N2;         // (B,128,256)

    const int smemD = (64*68  + 4*16*32 + 4*32) * 4;   // 26112 B
    const int smemF = (64*132 + 4*16*64 + 4*64) * 4;   // 51200 B
    const int smemH = (128*132 + 2*16*64 + 2*64) * 4;  // 76288 B
    cudaFuncSetAttribute(kernelF, cudaFuncAttributeMaxDynamicSharedMemorySize, smemF);
    cudaFuncSetAttribute(kernelH, cudaFuncAttributeMaxDynamicSharedMemorySize, smemH);

    kernelA<<<69, 512>>>(pc, Wt, bt);                  // fps1+fps2 (dual) || knn1+feat || zero
    kernelB<<<4192, 256>>>(pc, W1);                    // edge1 || gather qc1
    kernelC<<<4200, 256>>>(pc, g1, b1);                // knn2split||knn3||knn4||finalize1
    kernelD<<<2048, 256, smemD>>>(W2);                 // edge2
    kernelE<<<2048, 256>>>(g2, b2);                    // finalize2 -> qf2
    kernelF<<<2048, 256, smemF>>>(W3);                 // edge3
    kernelG<<<2072, 256>>>(g3, b3, qc_out);            // finalize3 -> kf3 || qc_out
    kernelH<<<1024, 256, smemH>>>(W4);                 // edge4
    kernelI<<<1024, 256>>>(g4, b4, qf_out);            // finalize4 -> qf_out
}